// round 1
// baseline (speedup 1.0000x reference)
#include <cuda_runtime.h>
#include <math.h>

#define NI 10000
#define H  128
#define L  50
#define B  64
#define E  160000
#define NC 9999
#define TN 96      // candidate tile per block in tail kernel

// ---------------- persistent device scratch (no allocations allowed) ----------------
__device__ float g_agg[NI * H];        // GCN segment sums
__device__ float g_sg [B * L * H];     // sess_glob = relu(agg@gW.T+gb)[items]
__device__ float g_h0 [B * L * H];     // h = emb[items]
__device__ float g_ain[B * L * H];
__device__ float g_aout[B * L * H];
__device__ float g_inp[B * L * 2 * H]; // concat(inp_in, inp_out)
__device__ float g_final[B * L * H];
__device__ float g_last[B * H];
__device__ float g_u  [B * H];         // folded last/s_global branch of w3
__device__ float g_cT [NC * H];        // cand @ w_target_W.T
__device__ float g_cA [NC * H];        // cand @ w3_W[:, :H]

// ---------------- K1: zero agg ----------------
__global__ void k_zero() {
    int i = blockIdx.x * blockDim.x + threadIdx.x;
    if (i < NI * H) g_agg[i] = 0.f;
}

// ---------------- K2: edge scatter (msg = w * emb[col]; segment_sum by row) ----------------
__global__ void k_edge(const int* __restrict__ row, const int* __restrict__ col,
                       const float* __restrict__ w, const float* __restrict__ emb) {
    int i = blockIdx.x * blockDim.x + threadIdx.x;
    int e = i >> 7;
    int h = i & 127;
    if (e < E) {
        atomicAdd(&g_agg[row[e] * H + h], w[e] * emb[col[e] * H + h]);
    }
}

// ---------------- K3: per (b,l): sess_glob, h0, a_in, a_out ----------------
__global__ void k_sess(const int* __restrict__ items, const float* __restrict__ emb,
                       const float* __restrict__ gW, const float* __restrict__ gb,
                       const float* __restrict__ liW, const float* __restrict__ lib,
                       const float* __restrict__ loW, const float* __restrict__ lob) {
    int bl = blockIdx.x;
    int t  = threadIdx.x;           // 0..127
    __shared__ float ar[H], er[H];
    int item = items[bl];
    ar[t] = g_agg[item * H + t];
    er[t] = emb[item * H + t];
    __syncthreads();
    float s  = gb[t];
    float ai = lib[t];
    float ao = lob[t];
    const float* wg = gW  + t * H;
    const float* wi = liW + t * H;
    const float* wo = loW + t * H;
    #pragma unroll 8
    for (int k = 0; k < H; k++) {
        s  += ar[k] * wg[k];
        ai += er[k] * wi[k];
        ao += er[k] * wo[k];
    }
    g_sg  [bl * H + t] = fmaxf(s, 0.f);
    g_ain [bl * H + t] = ai;
    g_aout[bl * H + t] = ao;
    g_h0  [bl * H + t] = er[t];
}

// ---------------- K4: inp = adj @ [a_in | a_out] ----------------
__global__ void k_prop(const float* __restrict__ adj) {
    int bl = blockIdx.x;
    int b  = bl / L;
    int t  = threadIdx.x;           // 0..255
    __shared__ float a[L];
    if (t < L) a[t] = adj[bl * L + t];
    __syncthreads();
    const float* src = (t < H) ? g_ain : g_aout;
    int h = t & 127;
    float acc = 0.f;
    #pragma unroll 5
    for (int k = 0; k < L; k++)
        acc += a[k] * src[(b * L + k) * H + h];
    g_inp[bl * 2 * H + t] = acc;
}

// ---------------- K5: GRU gates + h update + pos-emb + final + last ----------------
__global__ void k_gru(const int* __restrict__ items, const int* __restrict__ lens,
                      const float* __restrict__ w_ih, const float* __restrict__ w_hh,
                      const float* __restrict__ b_ih, const float* __restrict__ b_hh,
                      const float* __restrict__ pos_emb) {
    int bl = blockIdx.x;
    int b = bl / L, l = bl % L;
    int t = threadIdx.x;            // 0..383
    __shared__ float inp[2 * H], hs[H], gi[3 * H], gh[3 * H];
    if (t < 2 * H) inp[t] = g_inp[bl * 2 * H + t];
    if (t < H)     hs[t]  = g_h0[bl * H + t];
    __syncthreads();
    {
        float a = b_ih[t];
        const float* wr = w_ih + t * 2 * H;
        #pragma unroll 8
        for (int c = 0; c < 2 * H; c++) a += inp[c] * wr[c];
        gi[t] = a;
        float g = b_hh[t];
        const float* wh = w_hh + t * H;
        #pragma unroll 8
        for (int k = 0; k < H; k++) g += hs[k] * wh[k];
        gh[t] = g;
    }
    __syncthreads();
    if (t < H) {
        float r = 1.f / (1.f + expf(-(gi[t] + gh[t])));
        float z = 1.f / (1.f + expf(-(gi[H + t] + gh[H + t])));
        float n = tanhf(gi[2 * H + t] + r * gh[2 * H + t]);
        float hn = n + z * (hs[t] - n);
        int item = items[bl];
        int len  = lens[b];
        int rev  = (item == 0) ? 0 : (len - 1 - l);
        float fin = g_sg[bl * H + t] + hn + pos_emb[rev * H + t];
        g_final[bl * H + t] = fin;
        if (l == len - 1) g_last[b * H + t] = fin;
    }
}

// ---------------- K6: MHA readout -> s_global, then u = last@W3b.T + s_global@W3c.T ----------------
// dyn smem layout (floats): fin[50*128] ks[50*128] vs[50*128] qs[128] att[8*64] ctx[128] sg[128] ls[128] | int its[64]
#define ATTN_SMEM ((3 * L * H + H + 8 * 64 + 3 * H) * 4 + 64 * 4)
__global__ void k_attn(const int* __restrict__ items,
                       const float* __restrict__ ipw, const float* __restrict__ ipb,
                       const float* __restrict__ opw, const float* __restrict__ opb,
                       const float* __restrict__ w3) {
    extern __shared__ float sm[];
    float* fin = sm;
    float* ks  = fin + L * H;
    float* vs  = ks + L * H;
    float* qs  = vs + L * H;
    float* att = qs + H;
    float* ctx = att + 8 * 64;
    float* sg  = ctx + H;
    float* ls  = sg + H;
    int*   its = (int*)(ls + H);

    int b = blockIdx.x, t = threadIdx.x;  // 256 threads
    for (int i = t; i < L * H; i += 256) fin[i] = g_final[b * L * H + i];
    if (t < H) ls[t] = g_last[b * H + t];
    if (t < L) its[t] = items[b * L + t];
    __syncthreads();

    if (t < H) {
        float a = ipb[t];
        const float* w = ipw + t * H;
        #pragma unroll 8
        for (int k = 0; k < H; k++) a += ls[k] * w[k];
        qs[t] = a;
    }
    for (int i = t; i < L * H; i += 256) {
        int l = i / H, j = i % H;
        float a = ipb[H + j], v = ipb[2 * H + j];
        const float* wk = ipw + (H + j) * H;
        const float* wv = ipw + (2 * H + j) * H;
        #pragma unroll 8
        for (int c = 0; c < H; c++) {
            float f = fin[l * H + c];
            a += f * wk[c];
            v += f * wv[c];
        }
        ks[i] = a;
        vs[i] = v;
    }
    __syncthreads();
    for (int i = t; i < 8 * L; i += 256) {
        int hd = i / L, l = i % L;
        float a = 0.f;
        #pragma unroll
        for (int d = 0; d < 16; d++) a += qs[hd * 16 + d] * ks[l * H + hd * 16 + d];
        att[hd * 64 + l] = (its[l] == 0) ? -INFINITY : a * 0.25f;
    }
    __syncthreads();
    if (t < 8) {
        float m = -INFINITY;
        for (int l = 0; l < L; l++) m = fmaxf(m, att[t * 64 + l]);
        float s = 0.f;
        for (int l = 0; l < L; l++) {
            float e = expf(att[t * 64 + l] - m);
            att[t * 64 + l] = e;
            s += e;
        }
        float inv = 1.f / s;
        for (int l = 0; l < L; l++) att[t * 64 + l] *= inv;
    }
    __syncthreads();
    if (t < H) {
        int hd = t / 16;
        float c = 0.f;
        for (int l = 0; l < L; l++) c += att[hd * 64 + l] * vs[l * H + t];
        ctx[t] = c;
    }
    __syncthreads();
    if (t < H) {
        float a = opb[t];
        const float* w = opw + t * H;
        #pragma unroll 8
        for (int k = 0; k < H; k++) a += ctx[k] * w[k];
        sg[t] = a;
    }
    __syncthreads();
    if (t < H) {
        float u = 0.f;
        const float* w1 = w3 + t * 3 * H + H;
        const float* w2 = w3 + t * 3 * H + 2 * H;
        #pragma unroll 8
        for (int k = 0; k < H; k++) u += ls[k] * w1[k] + sg[k] * w2[k];
        g_u[b * H + t] = u;
    }
}

// ---------------- K7: candT = cand@w_target_W.T ; candA = cand@w3_W[:, :H] ----------------
__global__ void k_cand(const float* __restrict__ emb, const float* __restrict__ wt,
                       const float* __restrict__ w3) {
    int n = blockIdx.x;             // 0..9998
    int t = threadIdx.x;            // 0..127
    __shared__ float c[H];
    c[t] = emb[(n + 1) * H + t];
    __syncthreads();
    float a = 0.f, d = 0.f;
    const float* wr = wt + t * H;
    #pragma unroll 8
    for (int k = 0; k < H; k++) a += c[k] * wr[k];
    #pragma unroll 8
    for (int k = 0; k < H; k++) d += c[k] * w3[k * 3 * H + t];
    g_cT[n * H + t] = a;
    g_cA[n * H + t] = d;
}

// ---------------- K8: fused tail ----------------
// S[l,n] = final[b,l].candT[n] ; G[l,n] = final[b,l].candA[n]
// scores[b,n] = sum_l softmax_l(S)[l] * G[l,n] + u[b].cand[n]
// dyn smem floats: fin[56*128] cT[96*129] cA[96*129] cd[96*129] S[50*96] G[50*96] u[128] | int its[64]
#define TAIL_SMEM ((56 * H + 3 * TN * 129 + 2 * L * TN + H) * 4 + 64 * 4)
__global__ void __launch_bounds__(256) k_tail(const int* __restrict__ items,
                                              const float* __restrict__ emb,
                                              float* __restrict__ out) {
    extern __shared__ float sm[];
    float* fin = sm;                       // 56*128 (rows >=50 zero pad)
    float* cT  = fin + 56 * H;             // 96*129
    float* cA  = cT + TN * 129;
    float* cd  = cA + TN * 129;
    float* Ssm = cd + TN * 129;            // 50*96
    float* Gsm = Ssm + L * TN;
    float* us  = Gsm + L * TN;             // 128
    int*   its = (int*)(us + H);

    int n0 = blockIdx.x * TN;
    int b  = blockIdx.y;
    int t  = threadIdx.x;                  // 256

    for (int i = t; i < 56 * H; i += 256)
        fin[i] = (i < L * H) ? g_final[b * L * H + i] : 0.f;
    for (int i = t; i < TN * H; i += 256) {
        int n = i / H, k = i % H;
        int gn = n0 + n;
        float vT = 0.f, vA = 0.f, vC = 0.f;
        if (gn < NC) {
            vT = g_cT[gn * H + k];
            vA = g_cA[gn * H + k];
            vC = emb[(gn + 1) * H + k];
        }
        cT[n * 129 + k] = vT;
        cA[n * 129 + k] = vA;
        cd[n * 129 + k] = vC;
    }
    if (t < H) us[t] = g_u[b * H + t];
    if (t < L) its[t] = items[b * L + t];
    __syncthreads();

    // phase 1: register-tiled dual GEMM (7 l-rows x 3 n-cols per thread)
    {
        int j = t & 31;
        int i = t >> 5;
        float aS[7][3], aG[7][3];
        #pragma unroll
        for (int r = 0; r < 7; r++)
            #pragma unroll
            for (int c = 0; c < 3; c++) { aS[r][c] = 0.f; aG[r][c] = 0.f; }

        #pragma unroll 4
        for (int k = 0; k < H; k++) {
            float fv[7];
            #pragma unroll
            for (int r = 0; r < 7; r++) fv[r] = fin[(i + 8 * r) * H + k];
            float tv[3], av[3];
            #pragma unroll
            for (int c = 0; c < 3; c++) {
                int n = j + 32 * c;
                tv[c] = cT[n * 129 + k];
                av[c] = cA[n * 129 + k];
            }
            #pragma unroll
            for (int r = 0; r < 7; r++)
                #pragma unroll
                for (int c = 0; c < 3; c++) {
                    aS[r][c] += fv[r] * tv[c];
                    aG[r][c] += fv[r] * av[c];
                }
        }
        #pragma unroll
        for (int r = 0; r < 7; r++) {
            int l = i + 8 * r;
            if (l < L) {
                #pragma unroll
                for (int c = 0; c < 3; c++) {
                    Ssm[l * TN + j + 32 * c] = aS[r][c];
                    Gsm[l * TN + j + 32 * c] = aG[r][c];
                }
            }
        }
    }
    __syncthreads();

    // phase 2: masked softmax over l, weighted G sum, + u.cand
    if (t < TN) {
        int gn = n0 + t;
        if (gn < NC) {
            float m = -INFINITY;
            for (int l = 0; l < L; l++)
                if (its[l] != 0) m = fmaxf(m, Ssm[l * TN + t]);
            float s = 0.f, acc = 0.f;
            for (int l = 0; l < L; l++) {
                if (its[l] != 0) {
                    float e = expf(Ssm[l * TN + t] - m);
                    s += e;
                    acc += e * Gsm[l * TN + t];
                }
            }
            float uc = 0.f;
            #pragma unroll 8
            for (int k = 0; k < H; k++) uc += us[k] * cd[t * 129 + k];
            out[b * NC + gn] = acc / s + uc;
        }
    }
}

// ---------------- host launcher ----------------
extern "C" void kernel_launch(void* const* d_in, const int* in_sizes, int n_in,
                              void* d_out, int out_size) {
    const int*   items = (const int*)d_in[0];
    const int*   lens  = (const int*)d_in[1];
    const float* adj   = (const float*)d_in[2];
    const int*   erow  = (const int*)d_in[3];
    const int*   ecol  = (const int*)d_in[4];
    const float* ew    = (const float*)d_in[5];
    const float* emb   = (const float*)d_in[6];
    const float* pos   = (const float*)d_in[7];
    const float* gW    = (const float*)d_in[8];
    const float* gb    = (const float*)d_in[9];
    const float* liW   = (const float*)d_in[10];
    const float* lib   = (const float*)d_in[11];
    const float* loW   = (const float*)d_in[12];
    const float* lob   = (const float*)d_in[13];
    const float* w_ih  = (const float*)d_in[14];
    const float* w_hh  = (const float*)d_in[15];
    const float* b_ih  = (const float*)d_in[16];
    const float* b_hh  = (const float*)d_in[17];
    const float* ipw   = (const float*)d_in[18];
    const float* ipb   = (const float*)d_in[19];
    const float* opw   = (const float*)d_in[20];
    const float* opb   = (const float*)d_in[21];
    const float* wt    = (const float*)d_in[22];
    const float* w3    = (const float*)d_in[23];
    float* out = (float*)d_out;

    cudaFuncSetAttribute(k_attn, cudaFuncAttributeMaxDynamicSharedMemorySize, ATTN_SMEM);
    cudaFuncSetAttribute(k_tail, cudaFuncAttributeMaxDynamicSharedMemorySize, TAIL_SMEM);

    k_zero<<<(NI * H + 255) / 256, 256>>>();
    k_edge<<<(E * H + 255) / 256, 256>>>(erow, ecol, ew, emb);
    k_cand<<<NC, 128>>>(emb, wt, w3);
    k_sess<<<B * L, 128>>>(items, emb, gW, gb, liW, lib, loW, lob);
    k_prop<<<B * L, 256>>>(adj);
    k_gru<<<B * L, 384>>>(items, lens, w_ih, w_hh, b_ih, b_hh, pos);
    k_attn<<<B, 256, ATTN_SMEM>>>(items, ipw, ipb, opw, opb, w3);
    k_tail<<<dim3((NC + TN - 1) / TN, B), 256, TAIL_SMEM>>>(items, emb, out);
}

// round 2
// speedup vs baseline: 4.2819x; 4.2819x over previous
#include <cuda_runtime.h>
#include <math.h>

#define NI 10000
#define H  128
#define L  50
#define B  64
#define E  160000
#define NC 9999
#define TN 96      // candidate tile per block in tail kernel

// ---------------- persistent device scratch ----------------
__device__ float g_agg[NI * H];
__device__ float g_hA [B * L * H];     // gathered g_agg[items]
__device__ float g_h0 [B * L * H];     // gathered emb[items]
__device__ float g_sg [B * L * H];
__device__ float g_ain[B * L * H];
__device__ float g_aout[B * L * H];
__device__ float g_inp[B * L * 2 * H];
__device__ float g_gi [B * L * 3 * H];
__device__ float g_gh [B * L * 3 * H];
__device__ float g_final[B * L * H];
__device__ float g_kv [B * L * 2 * H];
__device__ float g_last[B * H];
__device__ float g_u  [B * H];
__device__ float g_cT [NC * H];
__device__ float g_cA [NC * H];
__device__ float g_w3a[H * H];         // w3[:, :H] transposed -> [n][k]

// ---------------- K1: zero agg ----------------
__global__ void k_zero() {
    int i = blockIdx.x * blockDim.x + threadIdx.x;
    if (i < NI * H) g_agg[i] = 0.f;
}

// ---------------- K2: edge scatter ----------------
__global__ void k_edge(const int* __restrict__ row, const int* __restrict__ col,
                       const float* __restrict__ w, const float* __restrict__ emb) {
    int i = blockIdx.x * blockDim.x + threadIdx.x;
    int e = i >> 7;
    int h = i & 127;
    if (e < E) {
        atomicAdd(&g_agg[row[e] * H + h], w[e] * emb[col[e] * H + h]);
    }
}

// ---------------- transpose w3[:, :H] ----------------
__global__ void k_w3t(const float* __restrict__ w3) {
    int n = blockIdx.x, k = threadIdx.x;
    g_w3a[n * H + k] = w3[k * 3 * H + n];
}

// ---------------- gather ----------------
__global__ void k_gather(const int* __restrict__ items, const float* __restrict__ emb) {
    int i = blockIdx.x * blockDim.x + threadIdx.x;   // B*L*H
    int bl = i >> 7, t = i & 127;
    int item = items[bl];
    g_hA[i] = g_agg[item * H + t];
    g_h0[i] = emb [item * H + t];
}

// ---------------- generic tiled GEMM: C[M,N] = act(A[M,K] @ Bw[N,K]^T + bias) ----------------
__global__ void __launch_bounds__(256) k_gemm(const float* __restrict__ A,
                                              const float* __restrict__ Bw,
                                              const float* __restrict__ bias,
                                              float* __restrict__ C,
                                              int M, int N, int K, int relu) {
    __shared__ float As[64][33];
    __shared__ float Bs[64][33];
    int m0 = blockIdx.y * 64, n0 = blockIdx.x * 64;
    int tid = threadIdx.x;
    int tx = tid & 15, ty = tid >> 4;
    float acc[4][4] = {};
    for (int k0 = 0; k0 < K; k0 += 32) {
        #pragma unroll
        for (int i = 0; i < 8; i++) {
            int idx = tid + 256 * i;
            int m = idx >> 5, k = idx & 31;
            int gm = m0 + m;
            As[m][k] = (gm < M) ? A[gm * K + k0 + k] : 0.f;
        }
        #pragma unroll
        for (int i = 0; i < 8; i++) {
            int idx = tid + 256 * i;
            int n = idx >> 5, k = idx & 31;
            int gn = n0 + n;
            Bs[n][k] = (gn < N) ? Bw[gn * K + k0 + k] : 0.f;
        }
        __syncthreads();
        #pragma unroll
        for (int k = 0; k < 32; k++) {
            float a[4], b[4];
            #pragma unroll
            for (int r = 0; r < 4; r++) a[r] = As[ty * 4 + r][k];
            #pragma unroll
            for (int c = 0; c < 4; c++) b[c] = Bs[tx * 4 + c][k];
            #pragma unroll
            for (int r = 0; r < 4; r++)
                #pragma unroll
                for (int c = 0; c < 4; c++)
                    acc[r][c] += a[r] * b[c];
        }
        __syncthreads();
    }
    #pragma unroll
    for (int r = 0; r < 4; r++) {
        int gm = m0 + ty * 4 + r;
        if (gm < M) {
            #pragma unroll
            for (int c = 0; c < 4; c++) {
                int gn = n0 + tx * 4 + c;
                if (gn < N) {
                    float v = acc[r][c] + (bias ? bias[gn] : 0.f);
                    if (relu) v = fmaxf(v, 0.f);
                    C[gm * N + gn] = v;
                }
            }
        }
    }
}

// ---------------- K4: inp = adj @ [a_in | a_out] ----------------
__global__ void k_prop(const float* __restrict__ adj) {
    int bl = blockIdx.x;
    int b  = bl / L;
    int t  = threadIdx.x;           // 0..255
    __shared__ float a[L];
    if (t < L) a[t] = adj[bl * L + t];
    __syncthreads();
    const float* src = (t < H) ? g_ain : g_aout;
    int h = t & 127;
    float acc = 0.f;
    #pragma unroll 5
    for (int k = 0; k < L; k++)
        acc += a[k] * src[(b * L + k) * H + h];
    g_inp[bl * 2 * H + t] = acc;
}

// ---------------- GRU elementwise + pos emb + final + last ----------------
__global__ void k_gru_elem(const int* __restrict__ items, const int* __restrict__ lens,
                           const float* __restrict__ pos_emb) {
    int i = blockIdx.x * blockDim.x + threadIdx.x;   // B*L*H
    int bl = i >> 7, t = i & 127;
    int b = bl / L, l = bl % L;
    const float* gi = g_gi + bl * 3 * H;
    const float* gh = g_gh + bl * 3 * H;
    float r = 1.f / (1.f + expf(-(gi[t] + gh[t])));
    float z = 1.f / (1.f + expf(-(gi[H + t] + gh[H + t])));
    float n = tanhf(gi[2 * H + t] + r * gh[2 * H + t]);
    float h0 = g_h0[i];
    float hn = n + z * (h0 - n);
    int item = items[bl];
    int len  = lens[b];
    int rev  = (item == 0) ? 0 : (len - 1 - l);
    float fin = g_sg[i] + hn + pos_emb[rev * H + t];
    g_final[i] = fin;
    if (l == len - 1) g_last[b * H + t] = fin;
}

// ---------------- attention readout (q small; k/v precomputed in g_kv) ----------------
// dyn smem floats: kvs[50*256] qs[128] att[8*64] ctx[128] sg[128] ls[128] | int its[64]
#define ATTN_SMEM ((L * 2 * H + H + 8 * 64 + 3 * H) * 4 + 64 * 4)
__global__ void k_attn(const int* __restrict__ items,
                       const float* __restrict__ ipw, const float* __restrict__ ipb,
                       const float* __restrict__ opw, const float* __restrict__ opb,
                       const float* __restrict__ w3) {
    extern __shared__ float sm[];
    float* kvs = sm;                  // [l][256] : k then v
    float* qs  = kvs + L * 2 * H;
    float* att = qs + H;
    float* ctx = att + 8 * 64;
    float* sg  = ctx + H;
    float* ls  = sg + H;
    int*   its = (int*)(ls + H);

    int b = blockIdx.x, t = threadIdx.x;  // 256 threads
    for (int i = t; i < L * 2 * H; i += 256) kvs[i] = g_kv[b * L * 2 * H + i];
    if (t < H) ls[t] = g_last[b * H + t];
    if (t < L) its[t] = items[b * L + t];
    __syncthreads();

    if (t < H) {
        float a = ipb[t];
        const float* w = ipw + t * H;
        #pragma unroll 8
        for (int k = 0; k < H; k++) a += ls[k] * w[k];
        qs[t] = a;
    }
    __syncthreads();
    for (int i = t; i < 8 * L; i += 256) {
        int hd = i / L, l = i % L;
        float a = 0.f;
        #pragma unroll
        for (int d = 0; d < 16; d++) a += qs[hd * 16 + d] * kvs[l * 2 * H + hd * 16 + d];
        att[hd * 64 + l] = (its[l] == 0) ? -INFINITY : a * 0.25f;
    }
    __syncthreads();
    if (t < 8) {
        float m = -INFINITY;
        for (int l = 0; l < L; l++) m = fmaxf(m, att[t * 64 + l]);
        float s = 0.f;
        for (int l = 0; l < L; l++) {
            float e = expf(att[t * 64 + l] - m);
            att[t * 64 + l] = e;
            s += e;
        }
        float inv = 1.f / s;
        for (int l = 0; l < L; l++) att[t * 64 + l] *= inv;
    }
    __syncthreads();
    if (t < H) {
        int hd = t / 16;
        float c = 0.f;
        for (int l = 0; l < L; l++) c += att[hd * 64 + l] * kvs[l * 2 * H + H + t];
        ctx[t] = c;
    }
    __syncthreads();
    if (t < H) {
        float a = opb[t];
        const float* w = opw + t * H;
        #pragma unroll 8
        for (int k = 0; k < H; k++) a += ctx[k] * w[k];
        sg[t] = a;
    }
    __syncthreads();
    if (t < H) {
        float u = 0.f;
        const float* w1 = w3 + t * 3 * H + H;
        const float* w2 = w3 + t * 3 * H + 2 * H;
        #pragma unroll 8
        for (int k = 0; k < H; k++) u += ls[k] * w1[k] + sg[k] * w2[k];
        g_u[b * H + t] = u;
    }
}

// ---------------- fused tail ----------------
#define TAIL_SMEM ((56 * H + 3 * TN * 129 + 2 * L * TN + H) * 4 + 64 * 4)
__global__ void __launch_bounds__(256) k_tail(const int* __restrict__ items,
                                              const float* __restrict__ emb,
                                              float* __restrict__ out) {
    extern __shared__ float sm[];
    float* fin = sm;                       // 56*128 (rows >=50 zero pad)
    float* cT  = fin + 56 * H;             // 96*129
    float* cA  = cT + TN * 129;
    float* cd  = cA + TN * 129;
    float* Ssm = cd + TN * 129;            // 50*96
    float* Gsm = Ssm + L * TN;
    float* us  = Gsm + L * TN;             // 128
    int*   its = (int*)(us + H);

    int n0 = blockIdx.x * TN;
    int b  = blockIdx.y;
    int t  = threadIdx.x;                  // 256

    for (int i = t; i < 56 * H; i += 256)
        fin[i] = (i < L * H) ? g_final[b * L * H + i] : 0.f;
    for (int i = t; i < TN * H; i += 256) {
        int n = i / H, k = i % H;
        int gn = n0 + n;
        float vT = 0.f, vA = 0.f, vC = 0.f;
        if (gn < NC) {
            vT = g_cT[gn * H + k];
            vA = g_cA[gn * H + k];
            vC = emb[(gn + 1) * H + k];
        }
        cT[n * 129 + k] = vT;
        cA[n * 129 + k] = vA;
        cd[n * 129 + k] = vC;
    }
    if (t < H) us[t] = g_u[b * H + t];
    if (t < L) its[t] = items[b * L + t];
    __syncthreads();

    {
        int j = t & 31;
        int i = t >> 5;
        float aS[7][3], aG[7][3];
        #pragma unroll
        for (int r = 0; r < 7; r++)
            #pragma unroll
            for (int c = 0; c < 3; c++) { aS[r][c] = 0.f; aG[r][c] = 0.f; }

        #pragma unroll 4
        for (int k = 0; k < H; k++) {
            float fv[7];
            #pragma unroll
            for (int r = 0; r < 7; r++) fv[r] = fin[(i + 8 * r) * H + k];
            float tv[3], av[3];
            #pragma unroll
            for (int c = 0; c < 3; c++) {
                int n = j + 32 * c;
                tv[c] = cT[n * 129 + k];
                av[c] = cA[n * 129 + k];
            }
            #pragma unroll
            for (int r = 0; r < 7; r++)
                #pragma unroll
                for (int c = 0; c < 3; c++) {
                    aS[r][c] += fv[r] * tv[c];
                    aG[r][c] += fv[r] * av[c];
                }
        }
        #pragma unroll
        for (int r = 0; r < 7; r++) {
            int l = i + 8 * r;
            if (l < L) {
                #pragma unroll
                for (int c = 0; c < 3; c++) {
                    Ssm[l * TN + j + 32 * c] = aS[r][c];
                    Gsm[l * TN + j + 32 * c] = aG[r][c];
                }
            }
        }
    }
    __syncthreads();

    if (t < TN) {
        int gn = n0 + t;
        if (gn < NC) {
            float m = -INFINITY;
            for (int l = 0; l < L; l++)
                if (its[l] != 0) m = fmaxf(m, Ssm[l * TN + t]);
            float s = 0.f, acc = 0.f;
            for (int l = 0; l < L; l++) {
                if (its[l] != 0) {
                    float e = expf(Ssm[l * TN + t] - m);
                    s += e;
                    acc += e * Gsm[l * TN + t];
                }
            }
            float uc = 0.f;
            #pragma unroll 8
            for (int k = 0; k < H; k++) uc += us[k] * cd[t * 129 + k];
            out[b * NC + gn] = acc / s + uc;
        }
    }
}

// ---------------- host launcher ----------------
extern "C" void kernel_launch(void* const* d_in, const int* in_sizes, int n_in,
                              void* d_out, int out_size) {
    const int*   items = (const int*)d_in[0];
    const int*   lens  = (const int*)d_in[1];
    const float* adj   = (const float*)d_in[2];
    const int*   erow  = (const int*)d_in[3];
    const int*   ecol  = (const int*)d_in[4];
    const float* ew    = (const float*)d_in[5];
    const float* emb   = (const float*)d_in[6];
    const float* pos   = (const float*)d_in[7];
    const float* gW    = (const float*)d_in[8];
    const float* gb    = (const float*)d_in[9];
    const float* liW   = (const float*)d_in[10];
    const float* lib   = (const float*)d_in[11];
    const float* loW   = (const float*)d_in[12];
    const float* lob   = (const float*)d_in[13];
    const float* w_ih  = (const float*)d_in[14];
    const float* w_hh  = (const float*)d_in[15];
    const float* b_ih  = (const float*)d_in[16];
    const float* b_hh  = (const float*)d_in[17];
    const float* ipw   = (const float*)d_in[18];
    const float* ipb   = (const float*)d_in[19];
    const float* opw   = (const float*)d_in[20];
    const float* opb   = (const float*)d_in[21];
    const float* wt    = (const float*)d_in[22];
    const float* w3    = (const float*)d_in[23];
    float* out = (float*)d_out;

    cudaFuncSetAttribute(k_attn, cudaFuncAttributeMaxDynamicSharedMemorySize, ATTN_SMEM);
    cudaFuncSetAttribute(k_tail, cudaFuncAttributeMaxDynamicSharedMemorySize, TAIL_SMEM);

    float* p_hA;    cudaGetSymbolAddress((void**)&p_hA,    g_hA);
    float* p_h0;    cudaGetSymbolAddress((void**)&p_h0,    g_h0);
    float* p_sg;    cudaGetSymbolAddress((void**)&p_sg,    g_sg);
    float* p_ain;   cudaGetSymbolAddress((void**)&p_ain,   g_ain);
    float* p_aout;  cudaGetSymbolAddress((void**)&p_aout,  g_aout);
    float* p_inp;   cudaGetSymbolAddress((void**)&p_inp,   g_inp);
    float* p_gi;    cudaGetSymbolAddress((void**)&p_gi,    g_gi);
    float* p_gh;    cudaGetSymbolAddress((void**)&p_gh,    g_gh);
    float* p_final; cudaGetSymbolAddress((void**)&p_final, g_final);
    float* p_kv;    cudaGetSymbolAddress((void**)&p_kv,    g_kv);
    float* p_cT;    cudaGetSymbolAddress((void**)&p_cT,    g_cT);
    float* p_cA;    cudaGetSymbolAddress((void**)&p_cA,    g_cA);
    float* p_w3a;   cudaGetSymbolAddress((void**)&p_w3a,   g_w3a);

    const int M = B * L;   // 3200

    k_zero<<<(NI * H + 255) / 256, 256>>>();
    k_edge<<<(E * H + 255) / 256, 256>>>(erow, ecol, ew, emb);
    k_w3t<<<H, H>>>(w3);
    k_gather<<<(M * H) / 256, 256>>>(items, emb);

    dim3 gM(2, (M + 63) / 64);                 // N=128
    k_gemm<<<gM, 256>>>(p_hA, gW,  gb,  p_sg,   M, H, H, 1);
    k_gemm<<<gM, 256>>>(p_h0, liW, lib, p_ain,  M, H, H, 0);
    k_gemm<<<gM, 256>>>(p_h0, loW, lob, p_aout, M, H, H, 0);

    k_prop<<<M, 256>>>(adj);

    dim3 gG(6, (M + 63) / 64);                 // N=384
    k_gemm<<<gG, 256>>>(p_inp, w_ih, b_ih, p_gi, M, 3 * H, 2 * H, 0);
    k_gemm<<<gG, 256>>>(p_h0,  w_hh, b_hh, p_gh, M, 3 * H, H, 0);

    k_gru_elem<<<(M * H) / 256, 256>>>(items, lens, pos);

    dim3 gKV(4, (M + 63) / 64);                // N=256
    k_gemm<<<gKV, 256>>>(p_final, ipw + H * H, ipb + H, p_kv, M, 2 * H, H, 0);

    k_attn<<<B, 256, ATTN_SMEM>>>(items, ipw, ipb, opw, opb, w3);

    dim3 gC(2, (NC + 63) / 64);                // M=9999, N=128
    k_gemm<<<gC, 256>>>(emb + H, wt,    (const float*)nullptr, p_cT, NC, H, H, 0);
    k_gemm<<<gC, 256>>>(emb + H, p_w3a, (const float*)nullptr, p_cA, NC, H, H, 0);

    k_tail<<<dim3((NC + TN - 1) / TN, B), 256, TAIL_SMEM>>>(items, emb, out);
}

// round 3
// speedup vs baseline: 5.7958x; 1.3535x over previous
#include <cuda_runtime.h>
#include <math.h>

#define NI 10000
#define H  128
#define L  50
#define B  64
#define E  160000
#define NC 9999
#define TN 96      // candidate tile per block in tail kernel
#define BG 4       // batches per tail block

// ---------------- persistent device scratch ----------------
__device__ float g_agg[NI * H];
__device__ float g_hA [B * L * H];
__device__ float g_h0 [B * L * H];
__device__ float g_sg [B * L * H];
__device__ float g_ain[B * L * H];
__device__ float g_aout[B * L * H];
__device__ float g_inp[B * L * 2 * H];
__device__ float g_gi [B * L * 3 * H];
__device__ float g_gh [B * L * 3 * H];
__device__ float g_final[B * L * H];
__device__ float g_kv [B * L * 2 * H];
__device__ float g_last[B * H];
__device__ float g_u  [B * H];
__device__ float g_cT [NC * H];
__device__ float g_cA [NC * H];
__device__ float g_w3a[H * H];

// packed dual-fp32 FMA (Blackwell double-rate fp32 path; ptxas never emits it)
__device__ __forceinline__ void ffma2(unsigned long long& d, unsigned long long a,
                                      unsigned long long b) {
    asm("fma.rn.f32x2 %0, %1, %2, %0;" : "+l"(d) : "l"(a), "l"(b));
}
__device__ __forceinline__ float unpack_sum(unsigned long long v) {
    float lo, hi;
    asm("mov.b64 {%0, %1}, %2;" : "=f"(lo), "=f"(hi) : "l"(v));
    return lo + hi;
}

// ---------------- K2: edge scatter, vector red ----------------
__global__ void k_edge(const int* __restrict__ row, const int* __restrict__ col,
                       const float* __restrict__ w, const float* __restrict__ emb) {
    int i = blockIdx.x * blockDim.x + threadIdx.x;
    int e = i >> 5;          // warp = one edge
    int q = i & 31;          // float4 index within 128 dims
    if (e < E) {
        float ww = w[e];
        int r = row[e], c = col[e];
        float4 v = ((const float4*)(emb + c * H))[q];
        v.x *= ww; v.y *= ww; v.z *= ww; v.w *= ww;
        float* dst = &g_agg[r * H + q * 4];
        asm volatile("red.global.add.v4.f32 [%0], {%1, %2, %3, %4};"
                     :: "l"(dst), "f"(v.x), "f"(v.y), "f"(v.z), "f"(v.w)
                     : "memory");
    }
}

// ---------------- transpose w3[:, :H] ----------------
__global__ void k_w3t(const float* __restrict__ w3) {
    int n = blockIdx.x, k = threadIdx.x;
    g_w3a[n * H + k] = w3[k * 3 * H + n];
}

// ---------------- gather ----------------
__global__ void k_gather(const int* __restrict__ items, const float* __restrict__ emb) {
    int i = blockIdx.x * blockDim.x + threadIdx.x;
    int bl = i >> 7, t = i & 127;
    int item = items[bl];
    g_hA[i] = g_agg[item * H + t];
    g_h0[i] = emb [item * H + t];
}

// ---------------- generic tiled GEMM: C = act(A[M,K] @ Bw[N,K]^T + bias) ----------------
__global__ void __launch_bounds__(256) k_gemm(const float* __restrict__ A,
                                              const float* __restrict__ Bw,
                                              const float* __restrict__ bias,
                                              float* __restrict__ C,
                                              int M, int N, int K, int relu) {
    __shared__ float As[64][33];
    __shared__ float Bs[64][33];
    int m0 = blockIdx.y * 64, n0 = blockIdx.x * 64;
    int tid = threadIdx.x;
    int tx = tid & 15, ty = tid >> 4;
    float acc[4][4] = {};
    for (int k0 = 0; k0 < K; k0 += 32) {
        #pragma unroll
        for (int i = 0; i < 2; i++) {
            int f = tid + 256 * i;        // float4 id: 64 rows x 8 f4
            int m = f >> 3, k4 = f & 7;
            int gm = m0 + m;
            float4 v = make_float4(0.f, 0.f, 0.f, 0.f);
            if (gm < M) v = *(const float4*)&A[gm * K + k0 + k4 * 4];
            As[m][k4 * 4 + 0] = v.x; As[m][k4 * 4 + 1] = v.y;
            As[m][k4 * 4 + 2] = v.z; As[m][k4 * 4 + 3] = v.w;
        }
        #pragma unroll
        for (int i = 0; i < 2; i++) {
            int f = tid + 256 * i;
            int n = f >> 3, k4 = f & 7;
            int gn = n0 + n;
            float4 v = make_float4(0.f, 0.f, 0.f, 0.f);
            if (gn < N) v = *(const float4*)&Bw[gn * K + k0 + k4 * 4];
            Bs[n][k4 * 4 + 0] = v.x; Bs[n][k4 * 4 + 1] = v.y;
            Bs[n][k4 * 4 + 2] = v.z; Bs[n][k4 * 4 + 3] = v.w;
        }
        __syncthreads();
        #pragma unroll
        for (int k = 0; k < 32; k++) {
            float a[4], b[4];
            #pragma unroll
            for (int r = 0; r < 4; r++) a[r] = As[ty * 4 + r][k];
            #pragma unroll
            for (int c = 0; c < 4; c++) b[c] = Bs[tx * 4 + c][k];
            #pragma unroll
            for (int r = 0; r < 4; r++)
                #pragma unroll
                for (int c = 0; c < 4; c++)
                    acc[r][c] += a[r] * b[c];
        }
        __syncthreads();
    }
    #pragma unroll
    for (int r = 0; r < 4; r++) {
        int gm = m0 + ty * 4 + r;
        if (gm < M) {
            #pragma unroll
            for (int c = 0; c < 4; c++) {
                int gn = n0 + tx * 4 + c;
                if (gn < N) {
                    float v = acc[r][c] + (bias ? bias[gn] : 0.f);
                    if (relu) v = fmaxf(v, 0.f);
                    C[gm * N + gn] = v;
                }
            }
        }
    }
}

// ---------------- K4: inp = adj @ [a_in | a_out], per-session tiled ----------------
#define PROP_SMEM ((L * L + L * 2 * H) * 4)
__global__ void k_prop(const float* __restrict__ adj) {
    extern __shared__ float psm[];
    float* sA  = psm;            // [L][L]
    float* sin = psm + L * L;    // [L][2H]
    int b = blockIdx.x, t = threadIdx.x;   // 256 threads
    for (int i = t; i < L * L; i += 256) sA[i] = adj[b * L * L + i];
    for (int k = 0; k < L; k++) {
        float v = (t < H) ? g_ain[(b * L + k) * H + t]
                          : g_aout[(b * L + k) * H + (t - H)];
        sin[k * 2 * H + t] = v;
    }
    __syncthreads();
    for (int l = 0; l < L; l++) {
        float acc = 0.f;
        #pragma unroll 10
        for (int k = 0; k < L; k++)
            acc += sA[l * L + k] * sin[k * 2 * H + t];
        g_inp[(b * L + l) * 2 * H + t] = acc;
    }
}

// ---------------- GRU elementwise + pos emb + final + last ----------------
__global__ void k_gru_elem(const int* __restrict__ items, const int* __restrict__ lens,
                           const float* __restrict__ pos_emb) {
    int i = blockIdx.x * blockDim.x + threadIdx.x;
    int bl = i >> 7, t = i & 127;
    int b = bl / L, l = bl % L;
    const float* gi = g_gi + bl * 3 * H;
    const float* gh = g_gh + bl * 3 * H;
    float r = 1.f / (1.f + expf(-(gi[t] + gh[t])));
    float z = 1.f / (1.f + expf(-(gi[H + t] + gh[H + t])));
    float n = tanhf(gi[2 * H + t] + r * gh[2 * H + t]);
    float h0 = g_h0[i];
    float hn = n + z * (h0 - n);
    int item = items[bl];
    int len  = lens[b];
    int rev  = (item == 0) ? 0 : (len - 1 - l);
    float fin = g_sg[i] + hn + pos_emb[rev * H + t];
    g_final[i] = fin;
    if (l == len - 1) g_last[b * H + t] = fin;
}

// ---------------- attention readout -> g_u ----------------
#define ATTN_SMEM ((L * 2 * H + H + 8 * 64 + 3 * H) * 4 + 64 * 4)
__global__ void k_attn(const int* __restrict__ items,
                       const float* __restrict__ ipw, const float* __restrict__ ipb,
                       const float* __restrict__ opw, const float* __restrict__ opb,
                       const float* __restrict__ w3) {
    extern __shared__ float sm[];
    float* kvs = sm;
    float* qs  = kvs + L * 2 * H;
    float* att = qs + H;
    float* ctx = att + 8 * 64;
    float* sg  = ctx + H;
    float* ls  = sg + H;
    int*   its = (int*)(ls + H);

    int b = blockIdx.x, t = threadIdx.x;
    for (int i = t; i < L * 2 * H; i += 256) kvs[i] = g_kv[b * L * 2 * H + i];
    if (t < H) ls[t] = g_last[b * H + t];
    if (t < L) its[t] = items[b * L + t];
    __syncthreads();

    if (t < H) {
        float a = ipb[t];
        const float* w = ipw + t * H;
        #pragma unroll 8
        for (int k = 0; k < H; k++) a += ls[k] * w[k];
        qs[t] = a;
    }
    __syncthreads();
    for (int i = t; i < 8 * L; i += 256) {
        int hd = i / L, l = i % L;
        float a = 0.f;
        #pragma unroll
        for (int d = 0; d < 16; d++) a += qs[hd * 16 + d] * kvs[l * 2 * H + hd * 16 + d];
        att[hd * 64 + l] = (its[l] == 0) ? -INFINITY : a * 0.25f;
    }
    __syncthreads();
    if (t < 8) {
        float m = -INFINITY;
        for (int l = 0; l < L; l++) m = fmaxf(m, att[t * 64 + l]);
        float s = 0.f;
        for (int l = 0; l < L; l++) {
            float e = expf(att[t * 64 + l] - m);
            att[t * 64 + l] = e;
            s += e;
        }
        float inv = 1.f / s;
        for (int l = 0; l < L; l++) att[t * 64 + l] *= inv;
    }
    __syncthreads();
    if (t < H) {
        int hd = t / 16;
        float c = 0.f;
        for (int l = 0; l < L; l++) c += att[hd * 64 + l] * kvs[l * 2 * H + H + t];
        ctx[t] = c;
    }
    __syncthreads();
    if (t < H) {
        float a = opb[t];
        const float* w = opw + t * H;
        #pragma unroll 8
        for (int k = 0; k < H; k++) a += ctx[k] * w[k];
        sg[t] = a;
    }
    __syncthreads();
    if (t < H) {
        float u = 0.f;
        const float* w1 = w3 + t * 3 * H + H;
        const float* w2 = w3 + t * 3 * H + 2 * H;
        #pragma unroll 8
        for (int k = 0; k < H; k++) u += ls[k] * w1[k] + sg[k] * w2[k];
        g_u[b * H + t] = u;
    }
}

// ---------------- fused tail: dual GEMM (FFMA2) + masked softmax-weighted sum ----------------
// smem floats: cT[96*132] cA[96*132] fin[56*128] S[50*96] G[50*96] | int its[64]
#define TAIL_SMEM ((2 * TN * 132 + 56 * H + 2 * L * TN) * 4 + 64 * 4)
__global__ void __launch_bounds__(256) k_tail(const int* __restrict__ items,
                                              float* __restrict__ out) {
    extern __shared__ float sm[];
    float* cT  = sm;
    float* cA  = cT + TN * 132;
    float* fin = cA + TN * 132;          // 56 rows, zero-padded
    float* Ssm = fin + 56 * H;
    float* Gsm = Ssm + L * TN;
    int*   its = (int*)(Gsm + L * TN);

    int n0 = blockIdx.x * TN;
    int bg = blockIdx.y * BG;
    int t  = threadIdx.x;                // 256
    int j  = t & 31;
    int i0 = t >> 5;

    // load candidate tiles once (resident across BG batches)
    #pragma unroll
    for (int i = 0; i < 12; i++) {
        int f = t + 256 * i;             // 96 n x 32 f4
        int n = f >> 5, k4 = f & 31;
        int gn = n0 + n;
        float4 vT = make_float4(0.f, 0.f, 0.f, 0.f);
        float4 vA = vT;
        if (gn < NC) {
            vT = *(const float4*)&g_cT[gn * H + k4 * 4];
            vA = *(const float4*)&g_cA[gn * H + k4 * 4];
        }
        *(float4*)&cT[n * 132 + k4 * 4] = vT;
        *(float4*)&cA[n * 132 + k4 * 4] = vA;
    }

    for (int bi = 0; bi < BG; bi++) {
        int b = bg + bi;
        // load final_b (+ zero pad rows 50..55) and items
        #pragma unroll
        for (int i = 0; i < 7; i++) {
            int f = t + 256 * i;         // 56 rows x 32 f4
            int l = f >> 5, k4 = f & 31;
            float4 v = make_float4(0.f, 0.f, 0.f, 0.f);
            if (l < L) v = *(const float4*)&g_final[(b * L + l) * H + k4 * 4];
            *(float4*)&fin[l * H + k4 * 4] = v;
        }
        if (t < L) its[t] = items[b * L + t];
        __syncthreads();

        // phase 1: dual GEMM, 7 rows x 3 cols per thread, packed f32x2 along k
        {
            unsigned long long aS[7][3] = {}, aG[7][3] = {};
            #pragma unroll 4
            for (int k4 = 0; k4 < 32; k4++) {
                ulonglong2 fv[7];
                #pragma unroll
                for (int r = 0; r < 7; r++)
                    fv[r] = *(const ulonglong2*)&fin[(i0 + 8 * r) * H + k4 * 4];
                ulonglong2 tv[3], av[3];
                #pragma unroll
                for (int c = 0; c < 3; c++) {
                    int n = j + 32 * c;
                    tv[c] = *(const ulonglong2*)&cT[n * 132 + k4 * 4];
                    av[c] = *(const ulonglong2*)&cA[n * 132 + k4 * 4];
                }
                #pragma unroll
                for (int r = 0; r < 7; r++)
                    #pragma unroll
                    for (int c = 0; c < 3; c++) {
                        ffma2(aS[r][c], fv[r].x, tv[c].x);
                        ffma2(aS[r][c], fv[r].y, tv[c].y);
                        ffma2(aG[r][c], fv[r].x, av[c].x);
                        ffma2(aG[r][c], fv[r].y, av[c].y);
                    }
            }
            #pragma unroll
            for (int r = 0; r < 7; r++) {
                int l = i0 + 8 * r;
                if (l < L) {
                    #pragma unroll
                    for (int c = 0; c < 3; c++) {
                        Ssm[l * TN + j + 32 * c] = unpack_sum(aS[r][c]);
                        Gsm[l * TN + j + 32 * c] = unpack_sum(aG[r][c]);
                    }
                }
            }
        }
        __syncthreads();

        // phase 2: masked softmax over l, weighted G sum; += onto k_uc's output
        if (t < TN) {
            int gn = n0 + t;
            if (gn < NC) {
                float m = -INFINITY;
                for (int l = 0; l < L; l++)
                    if (its[l] != 0) m = fmaxf(m, Ssm[l * TN + t]);
                float s = 0.f, acc = 0.f;
                for (int l = 0; l < L; l++) {
                    if (its[l] != 0) {
                        float e = expf(Ssm[l * TN + t] - m);
                        s += e;
                        acc += e * Gsm[l * TN + t];
                    }
                }
                out[b * NC + gn] += acc / s;
            }
        }
        __syncthreads();
    }
}

// ---------------- host launcher ----------------
extern "C" void kernel_launch(void* const* d_in, const int* in_sizes, int n_in,
                              void* d_out, int out_size) {
    const int*   items = (const int*)d_in[0];
    const int*   lens  = (const int*)d_in[1];
    const float* adj   = (const float*)d_in[2];
    const int*   erow  = (const int*)d_in[3];
    const int*   ecol  = (const int*)d_in[4];
    const float* ew    = (const float*)d_in[5];
    const float* emb   = (const float*)d_in[6];
    const float* pos   = (const float*)d_in[7];
    const float* gW    = (const float*)d_in[8];
    const float* gb    = (const float*)d_in[9];
    const float* liW   = (const float*)d_in[10];
    const float* lib   = (const float*)d_in[11];
    const float* loW   = (const float*)d_in[12];
    const float* lob   = (const float*)d_in[13];
    const float* w_ih  = (const float*)d_in[14];
    const float* w_hh  = (const float*)d_in[15];
    const float* b_ih  = (const float*)d_in[16];
    const float* b_hh  = (const float*)d_in[17];
    const float* ipw   = (const float*)d_in[18];
    const float* ipb   = (const float*)d_in[19];
    const float* opw   = (const float*)d_in[20];
    const float* opb   = (const float*)d_in[21];
    const float* wt    = (const float*)d_in[22];
    const float* w3    = (const float*)d_in[23];
    float* out = (float*)d_out;

    cudaFuncSetAttribute(k_attn, cudaFuncAttributeMaxDynamicSharedMemorySize, ATTN_SMEM);
    cudaFuncSetAttribute(k_tail, cudaFuncAttributeMaxDynamicSharedMemorySize, TAIL_SMEM);
    cudaFuncSetAttribute(k_prop, cudaFuncAttributeMaxDynamicSharedMemorySize, PROP_SMEM);

    float* p_agg;   cudaGetSymbolAddress((void**)&p_agg,   g_agg);
    float* p_hA;    cudaGetSymbolAddress((void**)&p_hA,    g_hA);
    float* p_h0;    cudaGetSymbolAddress((void**)&p_h0,    g_h0);
    float* p_sg;    cudaGetSymbolAddress((void**)&p_sg,    g_sg);
    float* p_ain;   cudaGetSymbolAddress((void**)&p_ain,   g_ain);
    float* p_aout;  cudaGetSymbolAddress((void**)&p_aout,  g_aout);
    float* p_inp;   cudaGetSymbolAddress((void**)&p_inp,   g_inp);
    float* p_gi;    cudaGetSymbolAddress((void**)&p_gi,    g_gi);
    float* p_gh;    cudaGetSymbolAddress((void**)&p_gh,    g_gh);
    float* p_final; cudaGetSymbolAddress((void**)&p_final, g_final);
    float* p_kv;    cudaGetSymbolAddress((void**)&p_kv,    g_kv);
    float* p_u;     cudaGetSymbolAddress((void**)&p_u,     g_u);
    float* p_cT;    cudaGetSymbolAddress((void**)&p_cT,    g_cT);
    float* p_cA;    cudaGetSymbolAddress((void**)&p_cA,    g_cA);
    float* p_w3a;   cudaGetSymbolAddress((void**)&p_w3a,   g_w3a);

    const int M = B * L;   // 3200

    cudaMemsetAsync(p_agg, 0, NI * H * sizeof(float));
    k_edge<<<(E * 32 + 255) / 256, 256>>>(erow, ecol, ew, emb);
    k_w3t<<<H, H>>>(w3);
    k_gather<<<(M * H) / 256, 256>>>(items, emb);

    dim3 gM(2, (M + 63) / 64);
    k_gemm<<<gM, 256>>>(p_hA, gW,  gb,  p_sg,   M, H, H, 1);
    k_gemm<<<gM, 256>>>(p_h0, liW, lib, p_ain,  M, H, H, 0);
    k_gemm<<<gM, 256>>>(p_h0, loW, lob, p_aout, M, H, H, 0);

    k_prop<<<B, 256, PROP_SMEM>>>(adj);

    dim3 gG(6, (M + 63) / 64);
    k_gemm<<<gG, 256>>>(p_inp, w_ih, b_ih, p_gi, M, 3 * H, 2 * H, 0);
    k_gemm<<<gG, 256>>>(p_h0,  w_hh, b_hh, p_gh, M, 3 * H, H, 0);

    k_gru_elem<<<(M * H) / 256, 256>>>(items, lens, pos);

    dim3 gKV(4, (M + 63) / 64);
    k_gemm<<<gKV, 256>>>(p_final, ipw + H * H, ipb + H, p_kv, M, 2 * H, H, 0);

    k_attn<<<B, 256, ATTN_SMEM>>>(items, ipw, ipb, opw, opb, w3);

    dim3 gC(2, (NC + 63) / 64);
    k_gemm<<<gC, 256>>>(emb + H, wt,    (const float*)nullptr, p_cT, NC, H, H, 0);
    k_gemm<<<gC, 256>>>(emb + H, p_w3a, (const float*)nullptr, p_cA, NC, H, H, 0);

    // uc[b,n] = u[b].cand[n] -> pre-writes out; k_tail accumulates on top
    dim3 gU((NC + 63) / 64, 1);
    k_gemm<<<gU, 256>>>(p_u, emb + H, (const float*)nullptr, out, B, NC, H, 0);

    k_tail<<<dim3((NC + TN - 1) / TN, B / BG), 256, TAIL_SMEM>>>(items, out);
}

// round 5
// speedup vs baseline: 8.0283x; 1.3852x over previous
#include <cuda_runtime.h>
#include <cuda_bf16.h>
#include <math.h>
#include <stdint.h>

#define NI 10000
#define H  128
#define L  50
#define B  64
#define E  160000
#define NC 9999
#define NCP 10112     // NC padded to 128*79
#define LP 64         // L padded for MMA

// ---------------- persistent device scratch ----------------
__device__ float g_agg[NI * H];
__device__ int   g_mark[NI];
__device__ float g_hA [B * L * H];
__device__ float g_h0 [B * L * H];
__device__ float g_sg [B * L * H];
__device__ float g_ain[B * L * H];
__device__ float g_aout[B * L * H];
__device__ float g_inp[B * L * 2 * H];
__device__ float g_gi [B * L * 3 * H];
__device__ float g_gh [B * L * 3 * H];
__device__ float g_final[B * L * H];
__device__ float g_kv [B * L * 2 * H];
__device__ float g_last[B * H];
__device__ float g_u  [B * H];
__device__ float g_cT [NC * H];
__device__ float g_cA [NC * H];
__device__ float g_w3a[H * H];
// bf16 split operands for tensor-core tail
__device__ __nv_bfloat16 g_fh [B * LP * H];
__device__ __nv_bfloat16 g_fl [B * LP * H];
__device__ __nv_bfloat16 g_cTh[NCP * H];
__device__ __nv_bfloat16 g_cTl[NCP * H];
__device__ __nv_bfloat16 g_cAh[NCP * H];
__device__ __nv_bfloat16 g_cAl[NCP * H];

// ---------------- mark session items ----------------
__global__ void k_mark(const int* __restrict__ items) {
    int i = blockIdx.x * blockDim.x + threadIdx.x;
    if (i < B * L) g_mark[items[i]] = 1;
}

// ---------------- edge scatter, vector red, filtered ----------------
__global__ void k_edge(const int* __restrict__ row, const int* __restrict__ col,
                       const float* __restrict__ w, const float* __restrict__ emb) {
    int i = blockIdx.x * blockDim.x + threadIdx.x;
    int e = i >> 5;
    int q = i & 31;
    if (e < E) {
        int r = row[e];
        if (g_mark[r]) {
            float ww = w[e];
            int c = col[e];
            float4 v = ((const float4*)(emb + c * H))[q];
            v.x *= ww; v.y *= ww; v.z *= ww; v.w *= ww;
            float* dst = &g_agg[r * H + q * 4];
            asm volatile("red.global.add.v4.f32 [%0], {%1, %2, %3, %4};"
                         :: "l"(dst), "f"(v.x), "f"(v.y), "f"(v.z), "f"(v.w)
                         : "memory");
        }
    }
}

// ---------------- transpose w3[:, :H] ----------------
__global__ void k_w3t(const float* __restrict__ w3) {
    int n = blockIdx.x, k = threadIdx.x;
    g_w3a[n * H + k] = w3[k * 3 * H + n];
}

// ---------------- gather ----------------
__global__ void k_gather(const int* __restrict__ items, const float* __restrict__ emb) {
    int i = blockIdx.x * blockDim.x + threadIdx.x;
    int bl = i >> 7, t = i & 127;
    int item = items[bl];
    g_hA[i] = g_agg[item * H + t];
    g_h0[i] = emb [item * H + t];
}

// ---------------- generic tiled GEMM: C = act(A[M,K] @ Bw[N,K]^T + bias) ----------------
__global__ void __launch_bounds__(256) k_gemm(const float* __restrict__ A,
                                              const float* __restrict__ Bw,
                                              const float* __restrict__ bias,
                                              float* __restrict__ C,
                                              int M, int N, int K, int relu) {
    __shared__ float As[64][33];
    __shared__ float Bs[64][33];
    int m0 = blockIdx.y * 64, n0 = blockIdx.x * 64;
    int tid = threadIdx.x;
    int tx = tid & 15, ty = tid >> 4;
    float acc[4][4] = {};
    for (int k0 = 0; k0 < K; k0 += 32) {
        #pragma unroll
        for (int i = 0; i < 2; i++) {
            int f = tid + 256 * i;
            int m = f >> 3, k4 = f & 7;
            int gm = m0 + m;
            float4 v = make_float4(0.f, 0.f, 0.f, 0.f);
            if (gm < M) v = *(const float4*)&A[gm * K + k0 + k4 * 4];
            As[m][k4 * 4 + 0] = v.x; As[m][k4 * 4 + 1] = v.y;
            As[m][k4 * 4 + 2] = v.z; As[m][k4 * 4 + 3] = v.w;
        }
        #pragma unroll
        for (int i = 0; i < 2; i++) {
            int f = tid + 256 * i;
            int n = f >> 3, k4 = f & 7;
            int gn = n0 + n;
            float4 v = make_float4(0.f, 0.f, 0.f, 0.f);
            if (gn < N) v = *(const float4*)&Bw[gn * K + k0 + k4 * 4];
            Bs[n][k4 * 4 + 0] = v.x; Bs[n][k4 * 4 + 1] = v.y;
            Bs[n][k4 * 4 + 2] = v.z; Bs[n][k4 * 4 + 3] = v.w;
        }
        __syncthreads();
        #pragma unroll
        for (int k = 0; k < 32; k++) {
            float a[4], b[4];
            #pragma unroll
            for (int r = 0; r < 4; r++) a[r] = As[ty * 4 + r][k];
            #pragma unroll
            for (int c = 0; c < 4; c++) b[c] = Bs[tx * 4 + c][k];
            #pragma unroll
            for (int r = 0; r < 4; r++)
                #pragma unroll
                for (int c = 0; c < 4; c++)
                    acc[r][c] += a[r] * b[c];
        }
        __syncthreads();
    }
    #pragma unroll
    for (int r = 0; r < 4; r++) {
        int gm = m0 + ty * 4 + r;
        if (gm < M) {
            #pragma unroll
            for (int c = 0; c < 4; c++) {
                int gn = n0 + tx * 4 + c;
                if (gn < N) {
                    float v = acc[r][c] + (bias ? bias[gn] : 0.f);
                    if (relu) v = fmaxf(v, 0.f);
                    C[gm * N + gn] = v;
                }
            }
        }
    }
}

// ---------------- inp = adj @ [a_in | a_out], per-session tiled ----------------
#define PROP_SMEM ((L * L + L * 2 * H) * 4)
__global__ void k_prop(const float* __restrict__ adj) {
    extern __shared__ float psm[];
    float* sA  = psm;
    float* sin = psm + L * L;
    int b = blockIdx.x, t = threadIdx.x;
    for (int i = t; i < L * L; i += 256) sA[i] = adj[b * L * L + i];
    for (int k = 0; k < L; k++) {
        float v = (t < H) ? g_ain[(b * L + k) * H + t]
                          : g_aout[(b * L + k) * H + (t - H)];
        sin[k * 2 * H + t] = v;
    }
    __syncthreads();
    for (int l = 0; l < L; l++) {
        float acc = 0.f;
        #pragma unroll 10
        for (int k = 0; k < L; k++)
            acc += sA[l * L + k] * sin[k * 2 * H + t];
        g_inp[(b * L + l) * 2 * H + t] = acc;
    }
}

// ---------------- GRU elementwise + pos emb + final + last + bf16 split ----------------
__global__ void k_gru_elem(const int* __restrict__ items, const int* __restrict__ lens,
                           const float* __restrict__ pos_emb) {
    int i = blockIdx.x * blockDim.x + threadIdx.x;
    int bl = i >> 7, t = i & 127;
    int b = bl / L, l = bl % L;
    const float* gi = g_gi + bl * 3 * H;
    const float* gh = g_gh + bl * 3 * H;
    float r = 1.f / (1.f + expf(-(gi[t] + gh[t])));
    float z = 1.f / (1.f + expf(-(gi[H + t] + gh[H + t])));
    float n = tanhf(gi[2 * H + t] + r * gh[2 * H + t]);
    float h0 = g_h0[i];
    float hn = n + z * (h0 - n);
    int item = items[bl];
    int len  = lens[b];
    int rev  = (item == 0) ? 0 : (len - 1 - l);
    float fin = g_sg[i] + hn + pos_emb[rev * H + t];
    g_final[i] = fin;
    __nv_bfloat16 fh = __float2bfloat16(fin);
    g_fh[(b * LP + l) * H + t] = fh;
    g_fl[(b * LP + l) * H + t] = __float2bfloat16(fin - __bfloat162float(fh));
    if (l == len - 1) g_last[b * H + t] = fin;
}

// ---------------- candidate bf16 split convert ----------------
__global__ void k_cvt_cand() {
    int i = blockIdx.x * blockDim.x + threadIdx.x;   // NCP*H
    int n = i >> 7;
    float vT = 0.f, vA = 0.f;
    if (n < NC) { vT = g_cT[i]; vA = g_cA[i]; }
    __nv_bfloat16 th = __float2bfloat16(vT);
    __nv_bfloat16 ah = __float2bfloat16(vA);
    g_cTh[i] = th;
    g_cTl[i] = __float2bfloat16(vT - __bfloat162float(th));
    g_cAh[i] = ah;
    g_cAl[i] = __float2bfloat16(vA - __bfloat162float(ah));
}

// ---------------- attention readout -> g_u ----------------
#define ATTN_SMEM ((L * 2 * H + H + 8 * 64 + 3 * H) * 4 + 64 * 4)
__global__ void k_attn(const int* __restrict__ items,
                       const float* __restrict__ ipw, const float* __restrict__ ipb,
                       const float* __restrict__ opw, const float* __restrict__ opb,
                       const float* __restrict__ w3) {
    extern __shared__ float sm[];
    float* kvs = sm;
    float* qs  = kvs + L * 2 * H;
    float* att = qs + H;
    float* ctx = att + 8 * 64;
    float* sg  = ctx + H;
    float* ls  = sg + H;
    int*   its = (int*)(ls + H);

    int b = blockIdx.x, t = threadIdx.x;
    for (int i = t; i < L * 2 * H; i += 256) kvs[i] = g_kv[b * L * 2 * H + i];
    if (t < H) ls[t] = g_last[b * H + t];
    if (t < L) its[t] = items[b * L + t];
    __syncthreads();

    if (t < H) {
        float a = ipb[t];
        const float* w = ipw + t * H;
        #pragma unroll 8
        for (int k = 0; k < H; k++) a += ls[k] * w[k];
        qs[t] = a;
    }
    __syncthreads();
    for (int i = t; i < 8 * L; i += 256) {
        int hd = i / L, l = i % L;
        float a = 0.f;
        #pragma unroll
        for (int d = 0; d < 16; d++) a += qs[hd * 16 + d] * kvs[l * 2 * H + hd * 16 + d];
        att[hd * 64 + l] = (its[l] == 0) ? -INFINITY : a * 0.25f;
    }
    __syncthreads();
    if (t < 8) {
        float m = -INFINITY;
        for (int l = 0; l < L; l++) m = fmaxf(m, att[t * 64 + l]);
        float s = 0.f;
        for (int l = 0; l < L; l++) {
            float e = expf(att[t * 64 + l] - m);
            att[t * 64 + l] = e;
            s += e;
        }
        float inv = 1.f / s;
        for (int l = 0; l < L; l++) att[t * 64 + l] *= inv;
    }
    __syncthreads();
    if (t < H) {
        int hd = t / 16;
        float c = 0.f;
        for (int l = 0; l < L; l++) c += att[hd * 64 + l] * kvs[l * 2 * H + H + t];
        ctx[t] = c;
    }
    __syncthreads();
    if (t < H) {
        float a = opb[t];
        const float* w = opw + t * H;
        #pragma unroll 8
        for (int k = 0; k < H; k++) a += ctx[k] * w[k];
        sg[t] = a;
    }
    __syncthreads();
    if (t < H) {
        float u = 0.f;
        const float* w1 = w3 + t * 3 * H + H;
        const float* w2 = w3 + t * 3 * H + 2 * H;
        #pragma unroll 8
        for (int k = 0; k < H; k++) u += ls[k] * w1[k] + sg[k] * w2[k];
        g_u[b * H + t] = u;
    }
}

// ---------------- tensor-core tail ----------------
// smem: A[64x512] | B_S=cTh[128x256] | B_S2=cTl[128x256] | B_G=[cAh|cAl][128x512]
//       | Sst[64x132]f32 | Gst[64x132]f32 | its
#define T_SA   0
#define T_SBS  32768
#define T_SBS2 65536
#define T_SBG  98304
#define T_SST  163840
#define T_GST  (T_SST + 64 * 132 * 4)
#define T_ITS  (T_GST + 64 * 132 * 4)
#define TAIL_SMEM (T_ITS + 256)

__device__ __forceinline__ void ldsm_x4(uint32_t addr, uint32_t& r0, uint32_t& r1,
                                        uint32_t& r2, uint32_t& r3) {
    asm volatile("ldmatrix.sync.aligned.m8n8.x4.shared.b16 {%0,%1,%2,%3}, [%4];"
                 : "=r"(r0), "=r"(r1), "=r"(r2), "=r"(r3) : "r"(addr));
}
__device__ __forceinline__ void mma_bf16(float* d, uint32_t a0, uint32_t a1,
                                         uint32_t a2, uint32_t a3,
                                         uint32_t b0, uint32_t b1) {
    asm volatile(
        "mma.sync.aligned.m16n8k16.row.col.f32.bf16.bf16.f32 "
        "{%0,%1,%2,%3}, {%4,%5,%6,%7}, {%8,%9}, {%0,%1,%2,%3};"
        : "+f"(d[0]), "+f"(d[1]), "+f"(d[2]), "+f"(d[3])
        : "r"(a0), "r"(a1), "r"(a2), "r"(a3), "r"(b0), "r"(b1));
}
// swizzled chunk address: 16B chunks, XOR low-3 bits of chunk with row
__device__ __forceinline__ uint32_t swz(uint32_t base, int row, int ch, int rs_ch) {
    return base + (uint32_t)(row * rs_ch * 16 + (((ch) ^ (row & 7)) << 4));
}

__global__ void __launch_bounds__(256) k_tail(const int* __restrict__ items,
                                              float* __restrict__ out) {
    extern __shared__ char smc[];
    uint32_t sb = (uint32_t)__cvta_generic_to_shared(smc);
    float* Sst = (float*)(smc + T_SST);
    float* Gst = (float*)(smc + T_GST);
    int*   its = (int*)(smc + T_ITS);

    int n0 = blockIdx.x * 128;
    int bg = blockIdx.y * 8;
    int t  = threadIdx.x;
    int w  = t >> 5, lane = t & 31;
    int p  = w & 1, q = w >> 1;
    int Rb = 32 * p;
    int Nb = 32 * q;
    int mat = lane >> 3, rin = lane & 7;
    int g = lane >> 2, tg = lane & 3;

    // ---- load B tiles once (swizzled) ----
    #pragma unroll
    for (int it = 0; it < 8; it++) {          // cTh: 128 rows x 16 chunks
        int idx = t + 256 * it;
        int r = idx >> 4, c = idx & 15;
        uint4 v = *(const uint4*)&g_cTh[(n0 + r) * H + c * 8];
        *(uint4*)(smc + T_SBS + r * 256 + ((c ^ (r & 7)) << 4)) = v;
    }
    #pragma unroll
    for (int it = 0; it < 8; it++) {          // cTl: 128 rows x 16 chunks
        int idx = t + 256 * it;
        int r = idx >> 4, c = idx & 15;
        uint4 v = *(const uint4*)&g_cTl[(n0 + r) * H + c * 8];
        *(uint4*)(smc + T_SBS2 + r * 256 + ((c ^ (r & 7)) << 4)) = v;
    }
    #pragma unroll
    for (int it = 0; it < 16; it++) {         // B_G: 128 rows x 32 chunks [cAh|cAl]
        int idx = t + 256 * it;
        int r = idx >> 5, c = idx & 31;
        const __nv_bfloat16* src = (c < 16) ? &g_cAh[(n0 + r) * H + c * 8]
                                            : &g_cAl[(n0 + r) * H + (c - 16) * 8];
        uint4 v = *(const uint4*)src;
        *(uint4*)(smc + T_SBG + r * 512 + ((c ^ (r & 7)) << 4)) = v;
    }

    for (int bi = 0; bi < 8; bi++) {
        int b = bg + bi;
        // ---- load A = [fh|fl] for this batch (swizzled) ----
        #pragma unroll
        for (int it = 0; it < 8; it++) {      // 64 rows x 32 chunks
            int idx = t + 256 * it;
            int r = idx >> 5, c = idx & 31;
            const __nv_bfloat16* src = (c < 16) ? &g_fh[(b * LP + r) * H + c * 8]
                                                : &g_fl[(b * LP + r) * H + (c - 16) * 8];
            uint4 v = *(const uint4*)src;
            *(uint4*)(smc + T_SA + r * 512 + ((c ^ (r & 7)) << 4)) = v;
        }
        if (t < L) its[t] = items[b * L + t];
        __syncthreads();

        // ---- MMA mainloop ----
        // ks 0-7:  A=fh, B_S=cTh, B_G=cAh   (high*high)
        // ks 8-15: A=fl, B_S=cTh, B_G=cAh   (lowA*high)
        // ks16-23: A=fh, B_S=cTl, B_G=cAl   (high*lowB)
        float Sacc[2][4][4] = {}, Gacc[2][4][4] = {};
        for (int ks = 0; ks < 24; ks++) {
            int ach = (ks < 16) ? 2 * ks : 2 * (ks - 16);
            uint32_t a[2][4];
            #pragma unroll
            for (int mi = 0; mi < 2; mi++) {
                int row = Rb + 16 * mi + rin + ((mat & 1) << 3);
                ldsm_x4(swz(sb + T_SA, row, ach + (mat >> 1), 32),
                        a[mi][0], a[mi][1], a[mi][2], a[mi][3]);
            }
            int bch = ((ks & 7) << 1) + (ks >= 16 ? 16 : 0);
            uint32_t bg_[2][4];
            #pragma unroll
            for (int nh = 0; nh < 2; nh++) {
                int row = Nb + 16 * nh + rin + ((mat >> 1) << 3);
                ldsm_x4(swz(sb + T_SBG, row, bch + (mat & 1), 32),
                        bg_[nh][0], bg_[nh][1], bg_[nh][2], bg_[nh][3]);
            }
            #pragma unroll
            for (int mi = 0; mi < 2; mi++)
                #pragma unroll
                for (int j = 0; j < 4; j++)
                    mma_bf16(Gacc[mi][j], a[mi][0], a[mi][1], a[mi][2], a[mi][3],
                             bg_[j >> 1][2 * (j & 1)], bg_[j >> 1][2 * (j & 1) + 1]);
            {
                uint32_t sbase = sb + ((ks < 16) ? T_SBS : T_SBS2);
                int sch = ((ks & 7) << 1);
                uint32_t bs_[2][4];
                #pragma unroll
                for (int nh = 0; nh < 2; nh++) {
                    int row = Nb + 16 * nh + rin + ((mat >> 1) << 3);
                    ldsm_x4(swz(sbase, row, sch + (mat & 1), 16),
                            bs_[nh][0], bs_[nh][1], bs_[nh][2], bs_[nh][3]);
                }
                #pragma unroll
                for (int mi = 0; mi < 2; mi++)
                    #pragma unroll
                    for (int j = 0; j < 4; j++)
                        mma_bf16(Sacc[mi][j], a[mi][0], a[mi][1], a[mi][2], a[mi][3],
                                 bs_[j >> 1][2 * (j & 1)], bs_[j >> 1][2 * (j & 1) + 1]);
            }
        }
        __syncthreads();

        // ---- stage fragments ----
        #pragma unroll
        for (int mi = 0; mi < 2; mi++)
            #pragma unroll
            for (int j = 0; j < 4; j++) {
                int Rr = Rb + 16 * mi + g;
                int Cc = Nb + 8 * j + 2 * tg;
                *(float2*)&Sst[Rr * 132 + Cc] = make_float2(Sacc[mi][j][0], Sacc[mi][j][1]);
                *(float2*)&Sst[(Rr + 8) * 132 + Cc] = make_float2(Sacc[mi][j][2], Sacc[mi][j][3]);
                *(float2*)&Gst[Rr * 132 + Cc] = make_float2(Gacc[mi][j][0], Gacc[mi][j][1]);
                *(float2*)&Gst[(Rr + 8) * 132 + Cc] = make_float2(Gacc[mi][j][2], Gacc[mi][j][3]);
            }
        __syncthreads();

        // ---- masked softmax over l + weighted G sum ----
        if (t < 128) {
            int gn = n0 + t;
            if (gn < NC) {
                float m = -INFINITY;
                for (int l = 0; l < L; l++)
                    if (its[l] != 0) m = fmaxf(m, Sst[l * 132 + t]);
                float s = 0.f, acc = 0.f;
                for (int l = 0; l < L; l++)
                    if (its[l] != 0) {
                        float e = __expf(Sst[l * 132 + t] - m);
                        s += e;
                        acc += e * Gst[l * 132 + t];
                    }
                out[b * NC + gn] += acc / s;
            }
        }
        __syncthreads();
    }
}

// ---------------- host launcher ----------------
extern "C" void kernel_launch(void* const* d_in, const int* in_sizes, int n_in,
                              void* d_out, int out_size) {
    const int*   items = (const int*)d_in[0];
    const int*   lens  = (const int*)d_in[1];
    const float* adj   = (const float*)d_in[2];
    const int*   erow  = (const int*)d_in[3];
    const int*   ecol  = (const int*)d_in[4];
    const float* ew    = (const float*)d_in[5];
    const float* emb   = (const float*)d_in[6];
    const float* pos   = (const float*)d_in[7];
    const float* gW    = (const float*)d_in[8];
    const float* gb    = (const float*)d_in[9];
    const float* liW   = (const float*)d_in[10];
    const float* lib   = (const float*)d_in[11];
    const float* loW   = (const float*)d_in[12];
    const float* lob   = (const float*)d_in[13];
    const float* w_ih  = (const float*)d_in[14];
    const float* w_hh  = (const float*)d_in[15];
    const float* b_ih  = (const float*)d_in[16];
    const float* b_hh  = (const float*)d_in[17];
    const float* ipw   = (const float*)d_in[18];
    const float* ipb   = (const float*)d_in[19];
    const float* opw   = (const float*)d_in[20];
    const float* opb   = (const float*)d_in[21];
    const float* wt    = (const float*)d_in[22];
    const float* w3    = (const float*)d_in[23];
    float* out = (float*)d_out;

    cudaFuncSetAttribute(k_attn, cudaFuncAttributeMaxDynamicSharedMemorySize, ATTN_SMEM);
    cudaFuncSetAttribute(k_tail, cudaFuncAttributeMaxDynamicSharedMemorySize, TAIL_SMEM);
    cudaFuncSetAttribute(k_prop, cudaFuncAttributeMaxDynamicSharedMemorySize, PROP_SMEM);

    float* p_agg;   cudaGetSymbolAddress((void**)&p_agg,   g_agg);
    int*   p_mark;  cudaGetSymbolAddress((void**)&p_mark,  g_mark);
    float* p_hA;    cudaGetSymbolAddress((void**)&p_hA,    g_hA);
    float* p_h0;    cudaGetSymbolAddress((void**)&p_h0,    g_h0);
    float* p_sg;    cudaGetSymbolAddress((void**)&p_sg,    g_sg);
    float* p_ain;   cudaGetSymbolAddress((void**)&p_ain,   g_ain);
    float* p_aout;  cudaGetSymbolAddress((void**)&p_aout,  g_aout);
    float* p_inp;   cudaGetSymbolAddress((void**)&p_inp,   g_inp);
    float* p_gi;    cudaGetSymbolAddress((void**)&p_gi,    g_gi);
    float* p_gh;    cudaGetSymbolAddress((void**)&p_gh,    g_gh);
    float* p_final; cudaGetSymbolAddress((void**)&p_final, g_final);
    float* p_kv;    cudaGetSymbolAddress((void**)&p_kv,    g_kv);
    float* p_u;     cudaGetSymbolAddress((void**)&p_u,     g_u);
    float* p_cT;    cudaGetSymbolAddress((void**)&p_cT,    g_cT);
    float* p_cA;    cudaGetSymbolAddress((void**)&p_cA,    g_cA);
    float* p_w3a;   cudaGetSymbolAddress((void**)&p_w3a,   g_w3a);
    void*  p_fh;    cudaGetSymbolAddress(&p_fh,  g_fh);
    void*  p_fl;    cudaGetSymbolAddress(&p_fl,  g_fl);

    const int M = B * L;   // 3200

    // fork: side stream for candidate chain
    cudaStream_t s1;
    cudaEvent_t evA, evB;
    cudaStreamCreateWithFlags(&s1, cudaStreamNonBlocking);
    cudaEventCreateWithFlags(&evA, cudaEventDisableTiming);
    cudaEventCreateWithFlags(&evB, cudaEventDisableTiming);

    cudaEventRecord(evA, 0);
    cudaStreamWaitEvent(s1, evA, 0);

    // ---- side chain (candidates) on s1 ----
    k_w3t<<<H, H, 0, s1>>>(w3);
    {
        dim3 gC(2, (NC + 63) / 64);
        k_gemm<<<gC, 256, 0, s1>>>(emb + H, wt,    (const float*)nullptr, p_cT, NC, H, H, 0);
        k_gemm<<<gC, 256, 0, s1>>>(emb + H, p_w3a, (const float*)nullptr, p_cA, NC, H, H, 0);
    }
    k_cvt_cand<<<(NCP * H) / 256, 256, 0, s1>>>();
    cudaEventRecord(evB, s1);

    // ---- main chain ----
    cudaMemsetAsync(p_agg, 0, NI * H * sizeof(float));
    cudaMemsetAsync(p_mark, 0, NI * sizeof(int));
    cudaMemsetAsync(p_fh, 0, B * LP * H * sizeof(__nv_bfloat16));
    cudaMemsetAsync(p_fl, 0, B * LP * H * sizeof(__nv_bfloat16));
    k_mark<<<(B * L + 255) / 256, 256>>>(items);
    k_edge<<<(E * 32 + 255) / 256, 256>>>(erow, ecol, ew, emb);
    k_gather<<<(M * H) / 256, 256>>>(items, emb);

    dim3 gM(2, (M + 63) / 64);
    k_gemm<<<gM, 256>>>(p_hA, gW,  gb,  p_sg,   M, H, H, 1);
    k_gemm<<<gM, 256>>>(p_h0, liW, lib, p_ain,  M, H, H, 0);
    k_gemm<<<gM, 256>>>(p_h0, loW, lob, p_aout, M, H, H, 0);

    k_prop<<<B, 256, PROP_SMEM>>>(adj);

    dim3 gG(6, (M + 63) / 64);
    k_gemm<<<gG, 256>>>(p_inp, w_ih, b_ih, p_gi, M, 3 * H, 2 * H, 0);
    k_gemm<<<gG, 256>>>(p_h0,  w_hh, b_hh, p_gh, M, 3 * H, H, 0);

    k_gru_elem<<<(M * H) / 256, 256>>>(items, lens, pos);

    dim3 gKV(4, (M + 63) / 64);
    k_gemm<<<gKV, 256>>>(p_final, ipw + H * H, ipb + H, p_kv, M, 2 * H, H, 0);

    k_attn<<<B, 256, ATTN_SMEM>>>(items, ipw, ipb, opw, opb, w3);

    // uc[b,n] = u[b].cand[n] -> pre-writes out; k_tail accumulates
    dim3 gU((NC + 63) / 64, 1);
    k_gemm<<<gU, 256>>>(p_u, emb + H, (const float*)nullptr, out, B, NC, H, 0);

    // join and run tensor-core tail
    cudaStreamWaitEvent(0, evB, 0);
    k_tail<<<dim3(NCP / 128, B / 8), 256, TAIL_SMEM>>>(items, out);
}

// round 7
// speedup vs baseline: 8.2264x; 1.0247x over previous
#include <cuda_runtime.h>
#include <cuda_bf16.h>
#include <math.h>
#include <stdint.h>

#define NI 10000
#define H  128
#define L  50
#define B  64
#define E  160000
#define NC 9999
#define NCP 10112     // NC padded to 128*79
#define LP 64         // L padded for MMA

// ---------------- persistent device scratch ----------------
__device__ float g_agg[NI * H];
__device__ int   g_mark[NI];
__device__ float g_sg [B * L * H];        // pre-relu
__device__ float g_ao [B * L * 256];      // [ain|aout]
__device__ float g_cat[B * L * 384];      // [inp(256) | h0(128)]
__device__ float g_gates[B * L * 512];    // [r_sum | z_sum | i_n | h_n]
__device__ float g_final[B * L * H];
__device__ float g_kv [B * L * 2 * H];
__device__ float g_last[B * H];
__device__ float g_u  [B * H];
__device__ float g_cT [NC * H];
__device__ float g_cA [NC * H];
__device__ float g_w3a[H * H];
__device__ float g_Wc [512 * 384];
__device__ float g_bc [512];
__device__ float g_Wio[256 * 128];
__device__ float g_bio[256];
// bf16 split operands for tensor-core tail
__device__ __nv_bfloat16 g_fh [B * LP * H];
__device__ __nv_bfloat16 g_fl [B * LP * H];
__device__ __nv_bfloat16 g_cTh[NCP * H];
__device__ __nv_bfloat16 g_cTl[NCP * H];
__device__ __nv_bfloat16 g_cAh[NCP * H];
__device__ __nv_bfloat16 g_cAl[NCP * H];

// ---------------- mark session items ----------------
__global__ void k_mark(const int* __restrict__ items) {
    int i = blockIdx.x * blockDim.x + threadIdx.x;
    if (i < B * L) g_mark[items[i]] = 1;
}

// ---------------- edge scatter, vector red, filtered ----------------
__global__ void k_edge(const int* __restrict__ row, const int* __restrict__ col,
                       const float* __restrict__ w, const float* __restrict__ emb) {
    int i = blockIdx.x * blockDim.x + threadIdx.x;
    int e = i >> 5;
    int q = i & 31;
    if (e < E) {
        int r = row[e];
        if (g_mark[r]) {
            float ww = w[e];
            int c = col[e];
            float4 v = ((const float4*)(emb + c * H))[q];
            v.x *= ww; v.y *= ww; v.z *= ww; v.w *= ww;
            float* dst = &g_agg[r * H + q * 4];
            asm volatile("red.global.add.v4.f32 [%0], {%1, %2, %3, %4};"
                         :: "l"(dst), "f"(v.x), "f"(v.y), "f"(v.z), "f"(v.w)
                         : "memory");
        }
    }
}

// ---------------- transpose w3[:, :H] ----------------
__global__ void k_w3t(const float* __restrict__ w3) {
    int n = blockIdx.x, k = threadIdx.x;
    g_w3a[n * H + k] = w3[k * 3 * H + n];
}

// ---------------- build concat weights: Wc[512x384], Wio[256x128] ----------------
__global__ void k_prep(const float* __restrict__ liW, const float* __restrict__ lib,
                       const float* __restrict__ loW, const float* __restrict__ lob,
                       const float* __restrict__ w_ih, const float* __restrict__ w_hh,
                       const float* __restrict__ b_ih, const float* __restrict__ b_hh) {
    int n = blockIdx.x, k = threadIdx.x;   // k < 384
    if (n < 512) {
        int j = n & 127;
        int sec = n >> 7;                  // 0:r 1:z 2:i_n 3:h_n
        float v;
        if (sec <= 1) {
            int row = sec * 128 + j;
            v = (k < 256) ? w_ih[row * 256 + k] : w_hh[row * 128 + (k - 256)];
        } else if (sec == 2) {
            v = (k < 256) ? w_ih[(256 + j) * 256 + k] : 0.f;
        } else {
            v = (k < 256) ? 0.f : w_hh[(256 + j) * 128 + (k - 256)];
        }
        g_Wc[n * 384 + k] = v;
        if (k == 0) {
            float bb;
            if (sec == 0)      bb = b_ih[j] + b_hh[j];
            else if (sec == 1) bb = b_ih[128 + j] + b_hh[128 + j];
            else if (sec == 2) bb = b_ih[256 + j];
            else               bb = b_hh[256 + j];
            g_bc[n] = bb;
        }
    } else {
        int m = n - 512;                   // 0..255
        if (k < 128) {
            g_Wio[m * 128 + k] = (m < 128) ? liW[m * 128 + k] : loW[(m - 128) * 128 + k];
            if (k == 0) g_bio[m] = (m < 128) ? lib[m] : lob[m - 128];
        }
    }
}

// ---------------- generic tiled GEMM: C op= act(A[aidx[M],K] @ Bw[N,K]^T + bias) ----------------
__global__ void __launch_bounds__(256) k_gemm(const float* __restrict__ A,
                                              const float* __restrict__ Bw,
                                              const float* __restrict__ bias,
                                              float* __restrict__ C,
                                              int M, int N, int K, int relu,
                                              const int* __restrict__ aidx, int accum) {
    __shared__ float As[64][33];
    __shared__ float Bs[64][33];
    int m0 = blockIdx.y * 64, n0 = blockIdx.x * 64;
    int tid = threadIdx.x;
    int tx = tid & 15, ty = tid >> 4;
    float acc[4][4] = {};
    for (int k0 = 0; k0 < K; k0 += 32) {
        #pragma unroll
        for (int i = 0; i < 2; i++) {
            int f = tid + 256 * i;
            int m = f >> 3, k4 = f & 7;
            int gm = m0 + m;
            float4 v = make_float4(0.f, 0.f, 0.f, 0.f);
            if (gm < M) {
                int am = aidx ? aidx[gm] : gm;
                v = *(const float4*)&A[am * K + k0 + k4 * 4];
            }
            As[m][k4 * 4 + 0] = v.x; As[m][k4 * 4 + 1] = v.y;
            As[m][k4 * 4 + 2] = v.z; As[m][k4 * 4 + 3] = v.w;
        }
        #pragma unroll
        for (int i = 0; i < 2; i++) {
            int f = tid + 256 * i;
            int n = f >> 3, k4 = f & 7;
            int gn = n0 + n;
            float4 v = make_float4(0.f, 0.f, 0.f, 0.f);
            if (gn < N) v = *(const float4*)&Bw[gn * K + k0 + k4 * 4];
            Bs[n][k4 * 4 + 0] = v.x; Bs[n][k4 * 4 + 1] = v.y;
            Bs[n][k4 * 4 + 2] = v.z; Bs[n][k4 * 4 + 3] = v.w;
        }
        __syncthreads();
        #pragma unroll
        for (int k = 0; k < 32; k++) {
            float a[4], b[4];
            #pragma unroll
            for (int r = 0; r < 4; r++) a[r] = As[ty * 4 + r][k];
            #pragma unroll
            for (int c = 0; c < 4; c++) b[c] = Bs[tx * 4 + c][k];
            #pragma unroll
            for (int r = 0; r < 4; r++)
                #pragma unroll
                for (int c = 0; c < 4; c++)
                    acc[r][c] += a[r] * b[c];
        }
        __syncthreads();
    }
    #pragma unroll
    for (int r = 0; r < 4; r++) {
        int gm = m0 + ty * 4 + r;
        if (gm < M) {
            #pragma unroll
            for (int c = 0; c < 4; c++) {
                int gn = n0 + tx * 4 + c;
                if (gn < N) {
                    float v = acc[r][c] + (bias ? bias[gn] : 0.f);
                    if (relu) v = fmaxf(v, 0.f);
                    if (accum) C[gm * N + gn] += v;
                    else       C[gm * N + gn] = v;
                }
            }
        }
    }
}

// ---------------- inp = adj @ ao, + h0 gather, into g_cat ----------------
#define PROP_SMEM ((L * L + L * 256) * 4)
__global__ void k_prop(const float* __restrict__ adj, const int* __restrict__ items,
                       const float* __restrict__ emb) {
    extern __shared__ float psm[];
    float* sA  = psm;
    float* sin = psm + L * L;
    int b = blockIdx.x, t = threadIdx.x;   // 256 threads
    for (int i = t; i < L * L; i += 256) sA[i] = adj[b * L * L + i];
    for (int k = 0; k < L; k++) sin[k * 256 + t] = g_ao[(b * L + k) * 256 + t];
    __syncthreads();
    for (int l = 0; l < L; l++) {
        float acc = 0.f;
        #pragma unroll 10
        for (int k = 0; k < L; k++)
            acc += sA[l * L + k] * sin[k * 256 + t];
        g_cat[(b * L + l) * 384 + t] = acc;
    }
    for (int i = t; i < L * H; i += 256) {
        int l = i >> 7, tt = i & 127;
        g_cat[(b * L + l) * 384 + 256 + tt] = emb[items[b * L + l] * H + tt];
    }
}

// ---------------- GRU elementwise + relu(sg) + pos emb + final + last + bf16 split ----------------
__global__ void k_gru_elem(const int* __restrict__ items, const int* __restrict__ lens,
                           const float* __restrict__ pos_emb) {
    int i = blockIdx.x * blockDim.x + threadIdx.x;
    int bl = i >> 7, t = i & 127;
    int b = bl / L, l = bl % L;
    const float* g = g_gates + bl * 512;
    float r = 1.f / (1.f + expf(-g[t]));
    float z = 1.f / (1.f + expf(-g[128 + t]));
    float n = tanhf(g[256 + t] + r * g[384 + t]);
    float h0 = g_cat[bl * 384 + 256 + t];
    float hn = n + z * (h0 - n);
    int item = items[bl];
    int len  = lens[b];
    int rev  = (item == 0) ? 0 : (len - 1 - l);
    float fin = fmaxf(g_sg[i], 0.f) + hn + pos_emb[rev * H + t];
    g_final[i] = fin;
    __nv_bfloat16 fh = __float2bfloat16(fin);
    g_fh[(b * LP + l) * H + t] = fh;
    g_fl[(b * LP + l) * H + t] = __float2bfloat16(fin - __bfloat162float(fh));
    if (l == len - 1) g_last[b * H + t] = fin;
}

// ---------------- candidate bf16 split convert ----------------
__global__ void k_cvt_cand() {
    int i = blockIdx.x * blockDim.x + threadIdx.x;   // NCP*H
    int n = i >> 7;
    float vT = 0.f, vA = 0.f;
    if (n < NC) { vT = g_cT[i]; vA = g_cA[i]; }
    __nv_bfloat16 th = __float2bfloat16(vT);
    __nv_bfloat16 ah = __float2bfloat16(vA);
    g_cTh[i] = th;
    g_cTl[i] = __float2bfloat16(vT - __bfloat162float(th));
    g_cAh[i] = ah;
    g_cAl[i] = __float2bfloat16(vA - __bfloat162float(ah));
}

// ---------------- attention readout -> g_u ----------------
#define ATTN_SMEM ((L * 2 * H + H + 8 * 64 + 3 * H) * 4 + 64 * 4)
__global__ void k_attn(const int* __restrict__ items,
                       const float* __restrict__ ipw, const float* __restrict__ ipb,
                       const float* __restrict__ opw, const float* __restrict__ opb,
                       const float* __restrict__ w3) {
    extern __shared__ float sm[];
    float* kvs = sm;
    float* qs  = kvs + L * 2 * H;
    float* att = qs + H;
    float* ctx = att + 8 * 64;
    float* sg  = ctx + H;
    float* ls  = sg + H;
    int*   its = (int*)(ls + H);

    int b = blockIdx.x, t = threadIdx.x;
    for (int i = t; i < L * 2 * H; i += 256) kvs[i] = g_kv[b * L * 2 * H + i];
    if (t < H) ls[t] = g_last[b * H + t];
    if (t < L) its[t] = items[b * L + t];
    __syncthreads();

    if (t < H) {
        float a = ipb[t];
        const float* w = ipw + t * H;
        #pragma unroll 8
        for (int k = 0; k < H; k++) a += ls[k] * w[k];
        qs[t] = a;
    }
    __syncthreads();
    for (int i = t; i < 8 * L; i += 256) {
        int hd = i / L, l = i % L;
        float a = 0.f;
        #pragma unroll
        for (int d = 0; d < 16; d++) a += qs[hd * 16 + d] * kvs[l * 2 * H + hd * 16 + d];
        att[hd * 64 + l] = (its[l] == 0) ? -INFINITY : a * 0.25f;
    }
    __syncthreads();
    if (t < 8) {
        float m = -INFINITY;
        for (int l = 0; l < L; l++) m = fmaxf(m, att[t * 64 + l]);
        float s = 0.f;
        for (int l = 0; l < L; l++) {
            float e = expf(att[t * 64 + l] - m);
            att[t * 64 + l] = e;
            s += e;
        }
        float inv = 1.f / s;
        for (int l = 0; l < L; l++) att[t * 64 + l] *= inv;
    }
    __syncthreads();
    if (t < H) {
        int hd = t / 16;
        float c = 0.f;
        for (int l = 0; l < L; l++) c += att[hd * 64 + l] * kvs[l * 2 * H + H + t];
        ctx[t] = c;
    }
    __syncthreads();
    if (t < H) {
        float a = opb[t];
        const float* w = opw + t * H;
        #pragma unroll 8
        for (int k = 0; k < H; k++) a += ctx[k] * w[k];
        sg[t] = a;
    }
    __syncthreads();
    if (t < H) {
        float u = 0.f;
        const float* w1 = w3 + t * 3 * H + H;
        const float* w2 = w3 + t * 3 * H + 2 * H;
        #pragma unroll 8
        for (int k = 0; k < H; k++) u += ls[k] * w1[k] + sg[k] * w2[k];
        g_u[b * H + t] = u;
    }
}

// ---------------- tensor-core tail ----------------
#define T_SA   0
#define T_SBS  32768
#define T_SBS2 65536
#define T_SBG  98304
#define T_SST  163840
#define T_GST  (T_SST + 64 * 132 * 4)
#define T_ITS  (T_GST + 64 * 132 * 4)
#define TAIL_SMEM (T_ITS + 256)

__device__ __forceinline__ void ldsm_x4(uint32_t addr, uint32_t& r0, uint32_t& r1,
                                        uint32_t& r2, uint32_t& r3) {
    asm volatile("ldmatrix.sync.aligned.m8n8.x4.shared.b16 {%0,%1,%2,%3}, [%4];"
                 : "=r"(r0), "=r"(r1), "=r"(r2), "=r"(r3) : "r"(addr));
}
__device__ __forceinline__ void mma_bf16(float* d, uint32_t a0, uint32_t a1,
                                         uint32_t a2, uint32_t a3,
                                         uint32_t b0, uint32_t b1) {
    asm volatile(
        "mma.sync.aligned.m16n8k16.row.col.f32.bf16.bf16.f32 "
        "{%0,%1,%2,%3}, {%4,%5,%6,%7}, {%8,%9}, {%0,%1,%2,%3};"
        : "+f"(d[0]), "+f"(d[1]), "+f"(d[2]), "+f"(d[3])
        : "r"(a0), "r"(a1), "r"(a2), "r"(a3), "r"(b0), "r"(b1));
}
__device__ __forceinline__ uint32_t swz(uint32_t base, int row, int ch, int rs_ch) {
    return base + (uint32_t)(row * rs_ch * 16 + (((ch) ^ (row & 7)) << 4));
}

__global__ void __launch_bounds__(256) k_tail(const int* __restrict__ items,
                                              float* __restrict__ out) {
    extern __shared__ char smc[];
    uint32_t sb = (uint32_t)__cvta_generic_to_shared(smc);
    float* Sst = (float*)(smc + T_SST);
    float* Gst = (float*)(smc + T_GST);
    int*   its = (int*)(smc + T_ITS);

    int n0 = blockIdx.x * 128;
    int bg = blockIdx.y * 8;
    int t  = threadIdx.x;
    int w  = t >> 5, lane = t & 31;
    int p  = w & 1, q = w >> 1;
    int Rb = 32 * p;
    int Nb = 32 * q;
    int mat = lane >> 3, rin = lane & 7;
    int g = lane >> 2, tg = lane & 3;

    #pragma unroll
    for (int it = 0; it < 8; it++) {          // cTh
        int idx = t + 256 * it;
        int r = idx >> 4, c = idx & 15;
        uint4 v = *(const uint4*)&g_cTh[(n0 + r) * H + c * 8];
        *(uint4*)(smc + T_SBS + r * 256 + ((c ^ (r & 7)) << 4)) = v;
    }
    #pragma unroll
    for (int it = 0; it < 8; it++) {          // cTl
        int idx = t + 256 * it;
        int r = idx >> 4, c = idx & 15;
        uint4 v = *(const uint4*)&g_cTl[(n0 + r) * H + c * 8];
        *(uint4*)(smc + T_SBS2 + r * 256 + ((c ^ (r & 7)) << 4)) = v;
    }
    #pragma unroll
    for (int it = 0; it < 16; it++) {         // [cAh|cAl]
        int idx = t + 256 * it;
        int r = idx >> 5, c = idx & 31;
        const __nv_bfloat16* src = (c < 16) ? &g_cAh[(n0 + r) * H + c * 8]
                                            : &g_cAl[(n0 + r) * H + (c - 16) * 8];
        uint4 v = *(const uint4*)src;
        *(uint4*)(smc + T_SBG + r * 512 + ((c ^ (r & 7)) << 4)) = v;
    }

    for (int bi = 0; bi < 8; bi++) {
        int b = bg + bi;
        #pragma unroll
        for (int it = 0; it < 8; it++) {      // A=[fh|fl]
            int idx = t + 256 * it;
            int r = idx >> 5, c = idx & 31;
            const __nv_bfloat16* src = (c < 16) ? &g_fh[(b * LP + r) * H + c * 8]
                                                : &g_fl[(b * LP + r) * H + (c - 16) * 8];
            uint4 v = *(const uint4*)src;
            *(uint4*)(smc + T_SA + r * 512 + ((c ^ (r & 7)) << 4)) = v;
        }
        if (t < L) its[t] = items[b * L + t];
        __syncthreads();

        float Sacc[2][4][4] = {}, Gacc[2][4][4] = {};
        for (int ks = 0; ks < 24; ks++) {
            int ach = (ks < 16) ? 2 * ks : 2 * (ks - 16);
            uint32_t a[2][4];
            #pragma unroll
            for (int mi = 0; mi < 2; mi++) {
                int row = Rb + 16 * mi + rin + ((mat & 1) << 3);
                ldsm_x4(swz(sb + T_SA, row, ach + (mat >> 1), 32),
                        a[mi][0], a[mi][1], a[mi][2], a[mi][3]);
            }
            int bch = ((ks & 7) << 1) + (ks >= 16 ? 16 : 0);
            uint32_t bg_[2][4];
            #pragma unroll
            for (int nh = 0; nh < 2; nh++) {
                int row = Nb + 16 * nh + rin + ((mat >> 1) << 3);
                ldsm_x4(swz(sb + T_SBG, row, bch + (mat & 1), 32),
                        bg_[nh][0], bg_[nh][1], bg_[nh][2], bg_[nh][3]);
            }
            #pragma unroll
            for (int mi = 0; mi < 2; mi++)
                #pragma unroll
                for (int j = 0; j < 4; j++)
                    mma_bf16(Gacc[mi][j], a[mi][0], a[mi][1], a[mi][2], a[mi][3],
                             bg_[j >> 1][2 * (j & 1)], bg_[j >> 1][2 * (j & 1) + 1]);
            {
                uint32_t sbase = sb + ((ks < 16) ? T_SBS : T_SBS2);
                int sch = ((ks & 7) << 1);
                uint32_t bs_[2][4];
                #pragma unroll
                for (int nh = 0; nh < 2; nh++) {
                    int row = Nb + 16 * nh + rin + ((mat >> 1) << 3);
                    ldsm_x4(swz(sbase, row, sch + (mat & 1), 16),
                            bs_[nh][0], bs_[nh][1], bs_[nh][2], bs_[nh][3]);
                }
                #pragma unroll
                for (int mi = 0; mi < 2; mi++)
                    #pragma unroll
                    for (int j = 0; j < 4; j++)
                        mma_bf16(Sacc[mi][j], a[mi][0], a[mi][1], a[mi][2], a[mi][3],
                                 bs_[j >> 1][2 * (j & 1)], bs_[j >> 1][2 * (j & 1) + 1]);
            }
        }
        __syncthreads();

        #pragma unroll
        for (int mi = 0; mi < 2; mi++)
            #pragma unroll
            for (int j = 0; j < 4; j++) {
                int Rr = Rb + 16 * mi + g;
                int Cc = Nb + 8 * j + 2 * tg;
                *(float2*)&Sst[Rr * 132 + Cc] = make_float2(Sacc[mi][j][0], Sacc[mi][j][1]);
                *(float2*)&Sst[(Rr + 8) * 132 + Cc] = make_float2(Sacc[mi][j][2], Sacc[mi][j][3]);
                *(float2*)&Gst[Rr * 132 + Cc] = make_float2(Gacc[mi][j][0], Gacc[mi][j][1]);
                *(float2*)&Gst[(Rr + 8) * 132 + Cc] = make_float2(Gacc[mi][j][2], Gacc[mi][j][3]);
            }
        __syncthreads();

        if (t < 128) {
            int gn = n0 + t;
            if (gn < NC) {
                float m = -INFINITY;
                for (int l = 0; l < L; l++)
                    if (its[l] != 0) m = fmaxf(m, Sst[l * 132 + t]);
                float s = 0.f, acc = 0.f;
                for (int l = 0; l < L; l++)
                    if (its[l] != 0) {
                        float e = __expf(Sst[l * 132 + t] - m);
                        s += e;
                        acc += e * Gst[l * 132 + t];
                    }
                out[b * NC + gn] = acc / s;     // overwrite; u-term added later
            }
        }
        __syncthreads();
    }
}

// ---------------- host launcher ----------------
extern "C" void kernel_launch(void* const* d_in, const int* in_sizes, int n_in,
                              void* d_out, int out_size) {
    const int*   items = (const int*)d_in[0];
    const int*   lens  = (const int*)d_in[1];
    const float* adj   = (const float*)d_in[2];
    const int*   erow  = (const int*)d_in[3];
    const int*   ecol  = (const int*)d_in[4];
    const float* ew    = (const float*)d_in[5];
    const float* emb   = (const float*)d_in[6];
    const float* pos   = (const float*)d_in[7];
    const float* gW    = (const float*)d_in[8];
    const float* gb    = (const float*)d_in[9];
    const float* liW   = (const float*)d_in[10];
    const float* lib   = (const float*)d_in[11];
    const float* loW   = (const float*)d_in[12];
    const float* lob   = (const float*)d_in[13];
    const float* w_ih  = (const float*)d_in[14];
    const float* w_hh  = (const float*)d_in[15];
    const float* b_ih  = (const float*)d_in[16];
    const float* b_hh  = (const float*)d_in[17];
    const float* ipw   = (const float*)d_in[18];
    const float* ipb   = (const float*)d_in[19];
    const float* opw   = (const float*)d_in[20];
    const float* opb   = (const float*)d_in[21];
    const float* wt    = (const float*)d_in[22];
    const float* w3    = (const float*)d_in[23];
    float* out = (float*)d_out;

    // one-time resource creation (NOT during graph capture; first call only)
    static bool s_init = false;
    static cudaStream_t s1, s2, s3;
    static cudaEvent_t evRoot, evCand, evGru, evGE, evAttn;
    if (!s_init) {
        cudaStreamCreateWithFlags(&s1, cudaStreamNonBlocking);
        cudaStreamCreateWithFlags(&s2, cudaStreamNonBlocking);
        cudaStreamCreateWithFlags(&s3, cudaStreamNonBlocking);
        cudaEventCreateWithFlags(&evRoot, cudaEventDisableTiming);
        cudaEventCreateWithFlags(&evCand, cudaEventDisableTiming);
        cudaEventCreateWithFlags(&evGru,  cudaEventDisableTiming);
        cudaEventCreateWithFlags(&evGE,   cudaEventDisableTiming);
        cudaEventCreateWithFlags(&evAttn, cudaEventDisableTiming);
        cudaFuncSetAttribute(k_attn, cudaFuncAttributeMaxDynamicSharedMemorySize, ATTN_SMEM);
        cudaFuncSetAttribute(k_tail, cudaFuncAttributeMaxDynamicSharedMemorySize, TAIL_SMEM);
        cudaFuncSetAttribute(k_prop, cudaFuncAttributeMaxDynamicSharedMemorySize, PROP_SMEM);
        s_init = true;
    }

    float* p_agg;   cudaGetSymbolAddress((void**)&p_agg,   g_agg);
    int*   p_mark;  cudaGetSymbolAddress((void**)&p_mark,  g_mark);
    float* p_sg;    cudaGetSymbolAddress((void**)&p_sg,    g_sg);
    float* p_ao;    cudaGetSymbolAddress((void**)&p_ao,    g_ao);
    float* p_cat;   cudaGetSymbolAddress((void**)&p_cat,   g_cat);
    float* p_gates; cudaGetSymbolAddress((void**)&p_gates, g_gates);
    float* p_final; cudaGetSymbolAddress((void**)&p_final, g_final);
    float* p_kv;    cudaGetSymbolAddress((void**)&p_kv,    g_kv);
    float* p_u;     cudaGetSymbolAddress((void**)&p_u,     g_u);
    float* p_cT;    cudaGetSymbolAddress((void**)&p_cT,    g_cT);
    float* p_cA;    cudaGetSymbolAddress((void**)&p_cA,    g_cA);
    float* p_w3a;   cudaGetSymbolAddress((void**)&p_w3a,   g_w3a);
    float* p_Wc;    cudaGetSymbolAddress((void**)&p_Wc,    g_Wc);
    float* p_bc;    cudaGetSymbolAddress((void**)&p_bc,    g_bc);
    float* p_Wio;   cudaGetSymbolAddress((void**)&p_Wio,   g_Wio);
    float* p_bio;   cudaGetSymbolAddress((void**)&p_bio,   g_bio);
    void*  p_fh;    cudaGetSymbolAddress(&p_fh,  g_fh);
    void*  p_fl;    cudaGetSymbolAddress(&p_fl,  g_fl);

    const int M = B * L;   // 3200

    cudaEventRecord(evRoot, 0);
    cudaStreamWaitEvent(s1, evRoot, 0);
    cudaStreamWaitEvent(s2, evRoot, 0);

    // ---- s1: candidate chain ----
    k_w3t<<<H, H, 0, s1>>>(w3);
    {
        dim3 gC(2, (NC + 63) / 64);
        k_gemm<<<gC, 256, 0, s1>>>(emb + H, wt,    (const float*)nullptr, p_cT, NC, H, H, 0, nullptr, 0);
        k_gemm<<<gC, 256, 0, s1>>>(emb + H, p_w3a, (const float*)nullptr, p_cA, NC, H, H, 0, nullptr, 0);
    }
    k_cvt_cand<<<(NCP * H) / 256, 256, 0, s1>>>();
    cudaEventRecord(evCand, s1);

    // ---- s2: GRU chain (independent of edge scatter) ----
    k_prep<<<768, 384, 0, s2>>>(liW, lib, loW, lob, w_ih, w_hh, b_ih, b_hh);
    {
        dim3 gA(4, (M + 63) / 64);    // N=256: [ain|aout] = emb[items] @ Wio^T
        k_gemm<<<gA, 256, 0, s2>>>(emb, p_Wio, p_bio, p_ao, M, 256, H, 0, items, 0);
    }
    k_prop<<<B, 256, PROP_SMEM, s2>>>(adj, items, emb);
    {
        dim3 gG(8, (M + 63) / 64);    // N=512: gates = cat @ Wc^T
        k_gemm<<<gG, 256, 0, s2>>>(p_cat, p_Wc, p_bc, p_gates, M, 512, 384, 0, nullptr, 0);
    }
    cudaEventRecord(evGru, s2);

    // ---- s0: edge scatter + sg ----
    cudaMemsetAsync(p_agg, 0, NI * H * sizeof(float));
    cudaMemsetAsync(p_mark, 0, NI * sizeof(int));
    cudaMemsetAsync(p_fh, 0, B * LP * H * sizeof(__nv_bfloat16));
    cudaMemsetAsync(p_fl, 0, B * LP * H * sizeof(__nv_bfloat16));
    k_mark<<<(B * L + 255) / 256, 256>>>(items);
    k_edge<<<(E * 32 + 255) / 256, 256>>>(erow, ecol, ew, emb);
    {
        dim3 gS(2, (M + 63) / 64);    // sg_pre = agg[items] @ gW^T + gb (relu deferred)
        k_gemm<<<gS, 256>>>(p_agg, gW, gb, p_sg, M, H, H, 0, items, 0);
    }

    // join gru chain -> elementwise
    cudaStreamWaitEvent(0, evGru, 0);
    k_gru_elem<<<(M * H) / 256, 256>>>(items, lens, pos);
    cudaEventRecord(evGE, 0);

    // ---- s3: attention branch (parallel with tail) ----
    cudaStreamWaitEvent(s3, evGE, 0);
    {
        dim3 gKV(4, (M + 63) / 64);
        k_gemm<<<gKV, 256, 0, s3>>>(p_final, ipw + H * H, ipb + H, p_kv, M, 2 * H, H, 0, nullptr, 0);
    }
    k_attn<<<B, 256, ATTN_SMEM, s3>>>(items, ipw, ipb, opw, opb, w3);
    cudaEventRecord(evAttn, s3);

    // ---- s0: tensor-core tail (writes scores), then += u.cand ----
    cudaStreamWaitEvent(0, evCand, 0);
    k_tail<<<dim3(NCP / 128, B / 8), 256, TAIL_SMEM>>>(items, out);

    cudaStreamWaitEvent(0, evAttn, 0);
    {
        dim3 gU((NC + 63) / 64, 1);
        k_gemm<<<gU, 256>>>(p_u, emb + H, (const float*)nullptr, out, B, NC, H, 0, nullptr, 1);
    }
}

// round 8
// speedup vs baseline: 10.1873x; 1.2384x over previous
#include <cuda_runtime.h>
#include <cuda_bf16.h>
#include <cuda_fp16.h>
#include <math.h>
#include <stdint.h>

#define NI 10000
#define H  128
#define L  50
#define B  64
#define E  160000
#define NC 9999
#define NCP 10112     // NC padded to 128*79
#define LP 64         // L padded for MMA

// ---------------- persistent device scratch ----------------
__device__ float g_agg[NI * H];
__device__ int   g_mark[NI];
__device__ float g_sg [B * L * H];        // pre-relu
__device__ float g_ao [B * L * 256];      // [ain|aout]
__device__ float g_cat[B * L * 384];      // [inp(256) | h0(128)]
__device__ float g_gates[B * L * 512];    // [r_sum | z_sum | i_n | h_n]
__device__ float g_final[B * L * H];
__device__ float g_kv [B * L * 2 * H];
__device__ float g_last[B * H];
__device__ float g_u  [B * H];
__device__ float g_cT [NC * H];
__device__ float g_cA [NC * H];
__device__ float g_w3a[H * H];
__device__ float g_Wc [512 * 384];
__device__ float g_bc [512];
__device__ float g_Wio[256 * 128];
__device__ float g_bio[256];
// fp16 operands for tensor-core tail (final error-compensated, candidates single)
__device__ __half g_fh [B * LP * H];
__device__ __half g_fl [B * LP * H];
__device__ __half g_cTh[NCP * H];
__device__ __half g_cAh[NCP * H];

// ---------------- mark session items ----------------
__global__ void k_mark(const int* __restrict__ items) {
    int i = blockIdx.x * blockDim.x + threadIdx.x;
    if (i < B * L) g_mark[items[i]] = 1;
}

// ---------------- edge scatter, vector red, filtered ----------------
__global__ void k_edge(const int* __restrict__ row, const int* __restrict__ col,
                       const float* __restrict__ w, const float* __restrict__ emb) {
    int i = blockIdx.x * blockDim.x + threadIdx.x;
    int e = i >> 5;
    int q = i & 31;
    if (e < E) {
        int r = row[e];
        if (g_mark[r]) {
            float ww = w[e];
            int c = col[e];
            float4 v = ((const float4*)(emb + c * H))[q];
            v.x *= ww; v.y *= ww; v.z *= ww; v.w *= ww;
            float* dst = &g_agg[r * H + q * 4];
            asm volatile("red.global.add.v4.f32 [%0], {%1, %2, %3, %4};"
                         :: "l"(dst), "f"(v.x), "f"(v.y), "f"(v.z), "f"(v.w)
                         : "memory");
        }
    }
}

// ---------------- transpose w3[:, :H] ----------------
__global__ void k_w3t(const float* __restrict__ w3) {
    int n = blockIdx.x, k = threadIdx.x;
    g_w3a[n * H + k] = w3[k * 3 * H + n];
}

// ---------------- build concat weights: Wc[512x384], Wio[256x128] ----------------
__global__ void k_prep(const float* __restrict__ liW, const float* __restrict__ lib,
                       const float* __restrict__ loW, const float* __restrict__ lob,
                       const float* __restrict__ w_ih, const float* __restrict__ w_hh,
                       const float* __restrict__ b_ih, const float* __restrict__ b_hh) {
    int n = blockIdx.x, k = threadIdx.x;   // k < 384
    if (n < 512) {
        int j = n & 127;
        int sec = n >> 7;                  // 0:r 1:z 2:i_n 3:h_n
        float v;
        if (sec <= 1) {
            int row = sec * 128 + j;
            v = (k < 256) ? w_ih[row * 256 + k] : w_hh[row * 128 + (k - 256)];
        } else if (sec == 2) {
            v = (k < 256) ? w_ih[(256 + j) * 256 + k] : 0.f;
        } else {
            v = (k < 256) ? 0.f : w_hh[(256 + j) * 128 + (k - 256)];
        }
        g_Wc[n * 384 + k] = v;
        if (k == 0) {
            float bb;
            if (sec == 0)      bb = b_ih[j] + b_hh[j];
            else if (sec == 1) bb = b_ih[128 + j] + b_hh[128 + j];
            else if (sec == 2) bb = b_ih[256 + j];
            else               bb = b_hh[256 + j];
            g_bc[n] = bb;
        }
    } else {
        int m = n - 512;                   // 0..255
        if (k < 128) {
            g_Wio[m * 128 + k] = (m < 128) ? liW[m * 128 + k] : loW[(m - 128) * 128 + k];
            if (k == 0) g_bio[m] = (m < 128) ? lib[m] : lob[m - 128];
        }
    }
}

// ---------------- generic tiled GEMM: C op= act(A[aidx[M],K] @ Bw[N,K]^T + bias) ----------------
__global__ void __launch_bounds__(256) k_gemm(const float* __restrict__ A,
                                              const float* __restrict__ Bw,
                                              const float* __restrict__ bias,
                                              float* __restrict__ C,
                                              int M, int N, int K, int relu,
                                              const int* __restrict__ aidx, int accum) {
    __shared__ float As[64][33];
    __shared__ float Bs[64][33];
    int m0 = blockIdx.y * 64, n0 = blockIdx.x * 64;
    int tid = threadIdx.x;
    int tx = tid & 15, ty = tid >> 4;
    float acc[4][4] = {};
    for (int k0 = 0; k0 < K; k0 += 32) {
        #pragma unroll
        for (int i = 0; i < 2; i++) {
            int f = tid + 256 * i;
            int m = f >> 3, k4 = f & 7;
            int gm = m0 + m;
            float4 v = make_float4(0.f, 0.f, 0.f, 0.f);
            if (gm < M) {
                int am = aidx ? aidx[gm] : gm;
                v = *(const float4*)&A[am * K + k0 + k4 * 4];
            }
            As[m][k4 * 4 + 0] = v.x; As[m][k4 * 4 + 1] = v.y;
            As[m][k4 * 4 + 2] = v.z; As[m][k4 * 4 + 3] = v.w;
        }
        #pragma unroll
        for (int i = 0; i < 2; i++) {
            int f = tid + 256 * i;
            int n = f >> 3, k4 = f & 7;
            int gn = n0 + n;
            float4 v = make_float4(0.f, 0.f, 0.f, 0.f);
            if (gn < N) v = *(const float4*)&Bw[gn * K + k0 + k4 * 4];
            Bs[n][k4 * 4 + 0] = v.x; Bs[n][k4 * 4 + 1] = v.y;
            Bs[n][k4 * 4 + 2] = v.z; Bs[n][k4 * 4 + 3] = v.w;
        }
        __syncthreads();
        #pragma unroll
        for (int k = 0; k < 32; k++) {
            float a[4], b[4];
            #pragma unroll
            for (int r = 0; r < 4; r++) a[r] = As[ty * 4 + r][k];
            #pragma unroll
            for (int c = 0; c < 4; c++) b[c] = Bs[tx * 4 + c][k];
            #pragma unroll
            for (int r = 0; r < 4; r++)
                #pragma unroll
                for (int c = 0; c < 4; c++)
                    acc[r][c] += a[r] * b[c];
        }
        __syncthreads();
    }
    #pragma unroll
    for (int r = 0; r < 4; r++) {
        int gm = m0 + ty * 4 + r;
        if (gm < M) {
            #pragma unroll
            for (int c = 0; c < 4; c++) {
                int gn = n0 + tx * 4 + c;
                if (gn < N) {
                    float v = acc[r][c] + (bias ? bias[gn] : 0.f);
                    if (relu) v = fmaxf(v, 0.f);
                    if (accum) C[gm * N + gn] += v;
                    else       C[gm * N + gn] = v;
                }
            }
        }
    }
}

// ---------------- inp = adj @ ao, + h0 gather, into g_cat ----------------
#define PROP_SMEM ((L * L + L * 256) * 4)
__global__ void k_prop(const float* __restrict__ adj, const int* __restrict__ items,
                       const float* __restrict__ emb) {
    extern __shared__ float psm[];
    float* sA  = psm;
    float* sin = psm + L * L;
    int b = blockIdx.x, t = threadIdx.x;   // 256 threads
    for (int i = t; i < L * L; i += 256) sA[i] = adj[b * L * L + i];
    for (int k = 0; k < L; k++) sin[k * 256 + t] = g_ao[(b * L + k) * 256 + t];
    __syncthreads();
    for (int l = 0; l < L; l++) {
        float acc = 0.f;
        #pragma unroll 10
        for (int k = 0; k < L; k++)
            acc += sA[l * L + k] * sin[k * 256 + t];
        g_cat[(b * L + l) * 384 + t] = acc;
    }
    for (int i = t; i < L * H; i += 256) {
        int l = i >> 7, tt = i & 127;
        g_cat[(b * L + l) * 384 + 256 + tt] = emb[items[b * L + l] * H + tt];
    }
}

// ---------------- GRU elementwise + relu(sg) + pos emb + final + last + fp16 split ----------------
__global__ void k_gru_elem(const int* __restrict__ items, const int* __restrict__ lens,
                           const float* __restrict__ pos_emb) {
    int i = blockIdx.x * blockDim.x + threadIdx.x;
    int bl = i >> 7, t = i & 127;
    int b = bl / L, l = bl % L;
    const float* g = g_gates + bl * 512;
    float r = 1.f / (1.f + expf(-g[t]));
    float z = 1.f / (1.f + expf(-g[128 + t]));
    float n = tanhf(g[256 + t] + r * g[384 + t]);
    float h0 = g_cat[bl * 384 + 256 + t];
    float hn = n + z * (h0 - n);
    int item = items[bl];
    int len  = lens[b];
    int rev  = (item == 0) ? 0 : (len - 1 - l);
    float fin = fmaxf(g_sg[i], 0.f) + hn + pos_emb[rev * H + t];
    g_final[i] = fin;
    __half fh = __float2half(fin);
    g_fh[(b * LP + l) * H + t] = fh;
    g_fl[(b * LP + l) * H + t] = __float2half(fin - __half2float(fh));
    if (l == len - 1) g_last[b * H + t] = fin;
}

// ---------------- candidate fp16 convert ----------------
__global__ void k_cvt_cand() {
    int i = blockIdx.x * blockDim.x + threadIdx.x;   // NCP*H
    int n = i >> 7;
    float vT = 0.f, vA = 0.f;
    if (n < NC) { vT = g_cT[i]; vA = g_cA[i]; }
    g_cTh[i] = __float2half(vT);
    g_cAh[i] = __float2half(vA);
}

// ---------------- attention readout -> g_u ----------------
#define ATTN_SMEM ((L * 2 * H + H + 8 * 64 + 3 * H) * 4 + 64 * 4)
__global__ void k_attn(const int* __restrict__ items,
                       const float* __restrict__ ipw, const float* __restrict__ ipb,
                       const float* __restrict__ opw, const float* __restrict__ opb,
                       const float* __restrict__ w3) {
    extern __shared__ float sm[];
    float* kvs = sm;
    float* qs  = kvs + L * 2 * H;
    float* att = qs + H;
    float* ctx = att + 8 * 64;
    float* sg  = ctx + H;
    float* ls  = sg + H;
    int*   its = (int*)(ls + H);

    int b = blockIdx.x, t = threadIdx.x;
    for (int i = t; i < L * 2 * H; i += 256) kvs[i] = g_kv[b * L * 2 * H + i];
    if (t < H) ls[t] = g_last[b * H + t];
    if (t < L) its[t] = items[b * L + t];
    __syncthreads();

    if (t < H) {
        float a = ipb[t];
        const float* w = ipw + t * H;
        #pragma unroll 8
        for (int k = 0; k < H; k++) a += ls[k] * w[k];
        qs[t] = a;
    }
    __syncthreads();
    for (int i = t; i < 8 * L; i += 256) {
        int hd = i / L, l = i % L;
        float a = 0.f;
        #pragma unroll
        for (int d = 0; d < 16; d++) a += qs[hd * 16 + d] * kvs[l * 2 * H + hd * 16 + d];
        att[hd * 64 + l] = (its[l] == 0) ? -INFINITY : a * 0.25f;
    }
    __syncthreads();
    if (t < 8) {
        float m = -INFINITY;
        for (int l = 0; l < L; l++) m = fmaxf(m, att[t * 64 + l]);
        float s = 0.f;
        for (int l = 0; l < L; l++) {
            float e = expf(att[t * 64 + l] - m);
            att[t * 64 + l] = e;
            s += e;
        }
        float inv = 1.f / s;
        for (int l = 0; l < L; l++) att[t * 64 + l] *= inv;
    }
    __syncthreads();
    if (t < H) {
        int hd = t / 16;
        float c = 0.f;
        for (int l = 0; l < L; l++) c += att[hd * 64 + l] * kvs[l * 2 * H + H + t];
        ctx[t] = c;
    }
    __syncthreads();
    if (t < H) {
        float a = opb[t];
        const float* w = opw + t * H;
        #pragma unroll 8
        for (int k = 0; k < H; k++) a += ctx[k] * w[k];
        sg[t] = a;
    }
    __syncthreads();
    if (t < H) {
        float u = 0.f;
        const float* w1 = w3 + t * 3 * H + H;
        const float* w2 = w3 + t * 3 * H + 2 * H;
        #pragma unroll 8
        for (int k = 0; k < H; k++) u += ls[k] * w1[k] + sg[k] * w2[k];
        g_u[b * H + t] = u;
    }
}

// ---------------- tensor-core tail (transposed: M=candidates, N=l) ----------------
// smem: cT[128x128 fp16]=32K | cA=32K | F=[fh|fl][64x256 fp16]=32K | its
#define T_CT  0
#define T_CA  32768
#define T_F   65536
#define T_ITS 98304
#define TAIL_SMEM (T_ITS + 256)

__device__ __forceinline__ void ldsm_x4(uint32_t addr, uint32_t& r0, uint32_t& r1,
                                        uint32_t& r2, uint32_t& r3) {
    asm volatile("ldmatrix.sync.aligned.m8n8.x4.shared.b16 {%0,%1,%2,%3}, [%4];"
                 : "=r"(r0), "=r"(r1), "=r"(r2), "=r"(r3) : "r"(addr));
}
__device__ __forceinline__ void mma_fp16(float* d, uint32_t a0, uint32_t a1,
                                         uint32_t a2, uint32_t a3,
                                         uint32_t b0, uint32_t b1) {
    asm volatile(
        "mma.sync.aligned.m16n8k16.row.col.f32.f16.f16.f32 "
        "{%0,%1,%2,%3}, {%4,%5,%6,%7}, {%8,%9}, {%0,%1,%2,%3};"
        : "+f"(d[0]), "+f"(d[1]), "+f"(d[2]), "+f"(d[3])
        : "r"(a0), "r"(a1), "r"(a2), "r"(a3), "r"(b0), "r"(b1));
}
__device__ __forceinline__ uint32_t swz(uint32_t base, int row, int ch, int rs_ch) {
    return base + (uint32_t)(row * rs_ch * 16 + (((ch) ^ (row & 7)) << 4));
}

__global__ void __launch_bounds__(256, 2) k_tail(const int* __restrict__ items,
                                                 float* __restrict__ out) {
    extern __shared__ char smc[];
    uint32_t sb = (uint32_t)__cvta_generic_to_shared(smc);
    int*   its = (int*)(smc + T_ITS);

    int n0 = blockIdx.x * 128;
    int bg = blockIdx.y * 8;
    int t  = threadIdx.x;
    int w  = t >> 5, lane = t & 31;
    int mat = lane >> 3, rin = lane & 7;
    int g = lane >> 2, tg = lane & 3;
    int Rm = 16 * w;                          // warp's candidate-tile base row

    // ---- load candidate operands once (fp16, swizzled, 16-chunk rows) ----
    #pragma unroll
    for (int it = 0; it < 8; it++) {
        int idx = t + 256 * it;
        int r = idx >> 4, c = idx & 15;
        uint4 v = *(const uint4*)&g_cTh[(n0 + r) * H + c * 8];
        *(uint4*)(smc + T_CT + r * 256 + ((c ^ (r & 7)) << 4)) = v;
    }
    #pragma unroll
    for (int it = 0; it < 8; it++) {
        int idx = t + 256 * it;
        int r = idx >> 4, c = idx & 15;
        uint4 v = *(const uint4*)&g_cAh[(n0 + r) * H + c * 8];
        *(uint4*)(smc + T_CA + r * 256 + ((c ^ (r & 7)) << 4)) = v;
    }

    for (int bi = 0; bi < 8; bi++) {
        int b = bg + bi;
        // ---- load F = [fh|fl] for this batch (32-chunk rows) ----
        #pragma unroll
        for (int it = 0; it < 8; it++) {
            int idx = t + 256 * it;
            int r = idx >> 5, c = idx & 31;
            const __half* src = (c < 16) ? &g_fh[(b * LP + r) * H + c * 8]
                                         : &g_fl[(b * LP + r) * H + (c - 16) * 8];
            uint4 v = *(const uint4*)src;
            *(uint4*)(smc + T_F + r * 512 + ((c ^ (r & 7)) << 4)) = v;
        }
        if (t < 64) its[t] = (t < L) ? items[b * L + t] : 0;
        __syncthreads();

        // ---- MMA mainloop: Sacc[j] / Gacc[j] over 8 l-tiles ----
        float Sacc[8][4] = {}, Gacc[8][4] = {};
        for (int kc = 0; kc < 8; kc++) {
            uint32_t aT[4], aA[4];
            int row_a = Rm + rin + ((mat & 1) << 3);
            int ch_a  = 2 * kc + (mat >> 1);
            ldsm_x4(swz(sb + T_CT, row_a, ch_a, 16), aT[0], aT[1], aT[2], aT[3]);
            ldsm_x4(swz(sb + T_CA, row_a, ch_a, 16), aA[0], aA[1], aA[2], aA[3]);
            int row_b = rin + ((mat >> 1) << 3);
            uint32_t bf[4][4];
            // fh half
            #pragma unroll
            for (int nh = 0; nh < 4; nh++)
                ldsm_x4(swz(sb + T_F, 16 * nh + row_b, 2 * kc + (mat & 1), 32),
                        bf[nh][0], bf[nh][1], bf[nh][2], bf[nh][3]);
            #pragma unroll
            for (int j = 0; j < 8; j++) {
                uint32_t b0 = bf[j >> 1][2 * (j & 1)], b1 = bf[j >> 1][2 * (j & 1) + 1];
                mma_fp16(Sacc[j], aT[0], aT[1], aT[2], aT[3], b0, b1);
                mma_fp16(Gacc[j], aA[0], aA[1], aA[2], aA[3], b0, b1);
            }
            // fl half (reuse bf regs)
            #pragma unroll
            for (int nh = 0; nh < 4; nh++)
                ldsm_x4(swz(sb + T_F, 16 * nh + row_b, 16 + 2 * kc + (mat & 1), 32),
                        bf[nh][0], bf[nh][1], bf[nh][2], bf[nh][3]);
            #pragma unroll
            for (int j = 0; j < 8; j++) {
                uint32_t b0 = bf[j >> 1][2 * (j & 1)], b1 = bf[j >> 1][2 * (j & 1) + 1];
                mma_fp16(Sacc[j], aT[0], aT[1], aT[2], aT[3], b0, b1);
                mma_fp16(Gacc[j], aA[0], aA[1], aA[2], aA[3], b0, b1);
            }
        }

        // ---- in-register masked softmax over l + weighted G sum ----
        // thread holds rows {g, g+8} x l-cols {8j+2tg, 8j+2tg+1}
        unsigned mk0 = 0, mk1 = 0;
        #pragma unroll
        for (int j = 0; j < 8; j++) {
            if (its[8 * j + 2 * tg] != 0)     mk0 |= (1u << j);
            if (its[8 * j + 2 * tg + 1] != 0) mk1 |= (1u << j);
        }
        #pragma unroll
        for (int h = 0; h < 2; h++) {
            float m = -INFINITY;
            #pragma unroll
            for (int j = 0; j < 8; j++) {
                if (mk0 & (1u << j)) m = fmaxf(m, Sacc[j][2 * h]);
                if (mk1 & (1u << j)) m = fmaxf(m, Sacc[j][2 * h + 1]);
            }
            m = fmaxf(m, __shfl_xor_sync(0xFFFFFFFF, m, 1));
            m = fmaxf(m, __shfl_xor_sync(0xFFFFFFFF, m, 2));
            float s = 0.f, acc = 0.f;
            #pragma unroll
            for (int j = 0; j < 8; j++) {
                if (mk0 & (1u << j)) {
                    float e = __expf(Sacc[j][2 * h] - m);
                    s += e; acc += e * Gacc[j][2 * h];
                }
                if (mk1 & (1u << j)) {
                    float e = __expf(Sacc[j][2 * h + 1] - m);
                    s += e; acc += e * Gacc[j][2 * h + 1];
                }
            }
            s   += __shfl_xor_sync(0xFFFFFFFF, s, 1);
            s   += __shfl_xor_sync(0xFFFFFFFF, s, 2);
            acc += __shfl_xor_sync(0xFFFFFFFF, acc, 1);
            acc += __shfl_xor_sync(0xFFFFFFFF, acc, 2);
            if (tg == 0) {
                int gn = n0 + Rm + g + 8 * h;
                if (gn < NC) out[b * NC + gn] = acc / s;
            }
        }
        __syncthreads();   // protect sF/its before next batch overwrites
    }
}

// ---------------- host launcher ----------------
extern "C" void kernel_launch(void* const* d_in, const int* in_sizes, int n_in,
                              void* d_out, int out_size) {
    const int*   items = (const int*)d_in[0];
    const int*   lens  = (const int*)d_in[1];
    const float* adj   = (const float*)d_in[2];
    const int*   erow  = (const int*)d_in[3];
    const int*   ecol  = (const int*)d_in[4];
    const float* ew    = (const float*)d_in[5];
    const float* emb   = (const float*)d_in[6];
    const float* pos   = (const float*)d_in[7];
    const float* gW    = (const float*)d_in[8];
    const float* gb    = (const float*)d_in[9];
    const float* liW   = (const float*)d_in[10];
    const float* lib   = (const float*)d_in[11];
    const float* loW   = (const float*)d_in[12];
    const float* lob   = (const float*)d_in[13];
    const float* w_ih  = (const float*)d_in[14];
    const float* w_hh  = (const float*)d_in[15];
    const float* b_ih  = (const float*)d_in[16];
    const float* b_hh  = (const float*)d_in[17];
    const float* ipw   = (const float*)d_in[18];
    const float* ipb   = (const float*)d_in[19];
    const float* opw   = (const float*)d_in[20];
    const float* opb   = (const float*)d_in[21];
    const float* wt    = (const float*)d_in[22];
    const float* w3    = (const float*)d_in[23];
    float* out = (float*)d_out;

    // one-time resource creation (NOT during graph capture; first call only)
    static bool s_init = false;
    static cudaStream_t s1, s2, s3;
    static cudaEvent_t evRoot, evCand, evGru, evGE, evAttn;
    if (!s_init) {
        cudaStreamCreateWithFlags(&s1, cudaStreamNonBlocking);
        cudaStreamCreateWithFlags(&s2, cudaStreamNonBlocking);
        cudaStreamCreateWithFlags(&s3, cudaStreamNonBlocking);
        cudaEventCreateWithFlags(&evRoot, cudaEventDisableTiming);
        cudaEventCreateWithFlags(&evCand, cudaEventDisableTiming);
        cudaEventCreateWithFlags(&evGru,  cudaEventDisableTiming);
        cudaEventCreateWithFlags(&evGE,   cudaEventDisableTiming);
        cudaEventCreateWithFlags(&evAttn, cudaEventDisableTiming);
        cudaFuncSetAttribute(k_attn, cudaFuncAttributeMaxDynamicSharedMemorySize, ATTN_SMEM);
        cudaFuncSetAttribute(k_tail, cudaFuncAttributeMaxDynamicSharedMemorySize, TAIL_SMEM);
        cudaFuncSetAttribute(k_prop, cudaFuncAttributeMaxDynamicSharedMemorySize, PROP_SMEM);
        s_init = true;
    }

    float* p_agg;   cudaGetSymbolAddress((void**)&p_agg,   g_agg);
    int*   p_mark;  cudaGetSymbolAddress((void**)&p_mark,  g_mark);
    float* p_sg;    cudaGetSymbolAddress((void**)&p_sg,    g_sg);
    float* p_ao;    cudaGetSymbolAddress((void**)&p_ao,    g_ao);
    float* p_cat;   cudaGetSymbolAddress((void**)&p_cat,   g_cat);
    float* p_gates; cudaGetSymbolAddress((void**)&p_gates, g_gates);
    float* p_final; cudaGetSymbolAddress((void**)&p_final, g_final);
    float* p_kv;    cudaGetSymbolAddress((void**)&p_kv,    g_kv);
    float* p_u;     cudaGetSymbolAddress((void**)&p_u,     g_u);
    float* p_cT;    cudaGetSymbolAddress((void**)&p_cT,    g_cT);
    float* p_cA;    cudaGetSymbolAddress((void**)&p_cA,    g_cA);
    float* p_w3a;   cudaGetSymbolAddress((void**)&p_w3a,   g_w3a);
    float* p_Wc;    cudaGetSymbolAddress((void**)&p_Wc,    g_Wc);
    float* p_bc;    cudaGetSymbolAddress((void**)&p_bc,    g_bc);
    float* p_Wio;   cudaGetSymbolAddress((void**)&p_Wio,   g_Wio);
    float* p_bio;   cudaGetSymbolAddress((void**)&p_bio,   g_bio);
    void*  p_fh;    cudaGetSymbolAddress(&p_fh,  g_fh);
    void*  p_fl;    cudaGetSymbolAddress(&p_fl,  g_fl);

    const int M = B * L;   // 3200

    cudaEventRecord(evRoot, 0);
    cudaStreamWaitEvent(s1, evRoot, 0);
    cudaStreamWaitEvent(s2, evRoot, 0);

    // ---- s1: candidate chain ----
    k_w3t<<<H, H, 0, s1>>>(w3);
    {
        dim3 gC(2, (NC + 63) / 64);
        k_gemm<<<gC, 256, 0, s1>>>(emb + H, wt,    (const float*)nullptr, p_cT, NC, H, H, 0, nullptr, 0);
        k_gemm<<<gC, 256, 0, s1>>>(emb + H, p_w3a, (const float*)nullptr, p_cA, NC, H, H, 0, nullptr, 0);
    }
    k_cvt_cand<<<(NCP * H) / 256, 256, 0, s1>>>();
    cudaEventRecord(evCand, s1);

    // ---- s2: GRU chain (independent of edge scatter) ----
    k_prep<<<768, 384, 0, s2>>>(liW, lib, loW, lob, w_ih, w_hh, b_ih, b_hh);
    {
        dim3 gA(4, (M + 63) / 64);    // N=256: [ain|aout] = emb[items] @ Wio^T
        k_gemm<<<gA, 256, 0, s2>>>(emb, p_Wio, p_bio, p_ao, M, 256, H, 0, items, 0);
    }
    k_prop<<<B, 256, PROP_SMEM, s2>>>(adj, items, emb);
    {
        dim3 gG(8, (M + 63) / 64);    // N=512: gates = cat @ Wc^T
        k_gemm<<<gG, 256, 0, s2>>>(p_cat, p_Wc, p_bc, p_gates, M, 512, 384, 0, nullptr, 0);
    }
    cudaEventRecord(evGru, s2);

    // ---- s0: edge scatter + sg ----
    cudaMemsetAsync(p_agg, 0, NI * H * sizeof(float));
    cudaMemsetAsync(p_mark, 0, NI * sizeof(int));
    cudaMemsetAsync(p_fh, 0, B * LP * H * sizeof(__half));
    cudaMemsetAsync(p_fl, 0, B * LP * H * sizeof(__half));
    k_mark<<<(B * L + 255) / 256, 256>>>(items);
    k_edge<<<(E * 32 + 255) / 256, 256>>>(erow, ecol, ew, emb);
    {
        dim3 gS(2, (M + 63) / 64);    // sg_pre = agg[items] @ gW^T + gb (relu deferred)
        k_gemm<<<gS, 256>>>(p_agg, gW, gb, p_sg, M, H, H, 0, items, 0);
    }

    // join gru chain -> elementwise
    cudaStreamWaitEvent(0, evGru, 0);
    k_gru_elem<<<(M * H) / 256, 256>>>(items, lens, pos);
    cudaEventRecord(evGE, 0);

    // ---- s3: attention branch (parallel with tail) ----
    cudaStreamWaitEvent(s3, evGE, 0);
    {
        dim3 gKV(4, (M + 63) / 64);
        k_gemm<<<gKV, 256, 0, s3>>>(p_final, ipw + H * H, ipb + H, p_kv, M, 2 * H, H, 0, nullptr, 0);
    }
    k_attn<<<B, 256, ATTN_SMEM, s3>>>(items, ipw, ipb, opw, opb, w3);
    cudaEventRecord(evAttn, s3);

    // ---- s0: tensor-core tail (writes scores), then += u.cand ----
    cudaStreamWaitEvent(0, evCand, 0);
    k_tail<<<dim3(NCP / 128, B / 8), 256, TAIL_SMEM>>>(items, out);

    cudaStreamWaitEvent(0, evAttn, 0);
    {
        dim3 gU((NC + 63) / 64, 1);
        k_gemm<<<gU, 256>>>(p_u, emb + H, (const float*)nullptr, out, B, NC, H, 0, nullptr, 1);
    }
}

// round 10
// speedup vs baseline: 10.3773x; 1.0187x over previous
#include <cuda_runtime.h>
#include <cuda_bf16.h>
#include <cuda_fp16.h>
#include <math.h>
#include <stdint.h>

#define NI 10000
#define H  128
#define L  50
#define B  64
#define E  160000
#define NC 9999
#define NCP 10112     // NC padded to 128*79
#define LP 64         // L padded for MMA

// ---------------- persistent device scratch ----------------
__device__ float g_agg[NI * H];
__device__ int   g_mark[NI];
__device__ float g_sg [B * L * H];        // pre-relu
__device__ float g_ao [B * L * 256];      // [ain|aout]
__device__ float g_cat[B * L * 384];      // [inp(256) | h0(128)]
__device__ float g_gates[B * L * 512];    // [r_sum | z_sum | i_n | h_n]
__device__ float g_final[B * L * H];
__device__ float g_kv [B * L * 2 * H];
__device__ float g_last[B * H];
__device__ float g_u  [B * H];
__device__ float g_uc [B * NC];           // u . cand^T (computed in parallel with tail)
__device__ float g_cT [NC * H];
__device__ float g_cA [NC * H];
__device__ float g_w3a[H * H];
__device__ float g_Wc [512 * 384];
__device__ float g_bc [512];
__device__ float g_Wio[256 * 128];
__device__ float g_bio[256];
// fp16 operands for tensor-core tail (final error-compensated, candidates single)
__device__ __half g_fh [B * LP * H];
__device__ __half g_fl [B * LP * H];
__device__ __half g_cTh[NCP * H];
__device__ __half g_cAh[NCP * H];

// ---------------- mark session items ----------------
__global__ void k_mark(const int* __restrict__ items) {
    int i = blockIdx.x * blockDim.x + threadIdx.x;
    if (i < B * L) g_mark[items[i]] = 1;
}

// ---------------- edge scatter, vector red, filtered ----------------
__global__ void k_edge(const int* __restrict__ row, const int* __restrict__ col,
                       const float* __restrict__ w, const float* __restrict__ emb) {
    int i = blockIdx.x * blockDim.x + threadIdx.x;
    int e = i >> 5;
    int q = i & 31;
    if (e < E) {
        int r = row[e];
        if (g_mark[r]) {
            float ww = w[e];
            int c = col[e];
            float4 v = ((const float4*)(emb + c * H))[q];
            v.x *= ww; v.y *= ww; v.z *= ww; v.w *= ww;
            float* dst = &g_agg[r * H + q * 4];
            asm volatile("red.global.add.v4.f32 [%0], {%1, %2, %3, %4};"
                         :: "l"(dst), "f"(v.x), "f"(v.y), "f"(v.z), "f"(v.w)
                         : "memory");
        }
    }
}

// ---------------- transpose w3[:, :H] ----------------
__global__ void k_w3t(const float* __restrict__ w3) {
    int n = blockIdx.x, k = threadIdx.x;
    g_w3a[n * H + k] = w3[k * 3 * H + n];
}

// ---------------- build concat weights: Wc[512x384], Wio[256x128] ----------------
__global__ void k_prep(const float* __restrict__ liW, const float* __restrict__ lib,
                       const float* __restrict__ loW, const float* __restrict__ lob,
                       const float* __restrict__ w_ih, const float* __restrict__ w_hh,
                       const float* __restrict__ b_ih, const float* __restrict__ b_hh) {
    int n = blockIdx.x, k = threadIdx.x;   // k < 384
    if (n < 512) {
        int j = n & 127;
        int sec = n >> 7;                  // 0:r 1:z 2:i_n 3:h_n
        float v;
        if (sec <= 1) {
            int row = sec * 128 + j;
            v = (k < 256) ? w_ih[row * 256 + k] : w_hh[row * 128 + (k - 256)];
        } else if (sec == 2) {
            v = (k < 256) ? w_ih[(256 + j) * 256 + k] : 0.f;
        } else {
            v = (k < 256) ? 0.f : w_hh[(256 + j) * 128 + (k - 256)];
        }
        g_Wc[n * 384 + k] = v;
        if (k == 0) {
            float bb;
            if (sec == 0)      bb = b_ih[j] + b_hh[j];
            else if (sec == 1) bb = b_ih[128 + j] + b_hh[128 + j];
            else if (sec == 2) bb = b_ih[256 + j];
            else               bb = b_hh[256 + j];
            g_bc[n] = bb;
        }
    } else {
        int m = n - 512;                   // 0..255
        if (k < 128) {
            g_Wio[m * 128 + k] = (m < 128) ? liW[m * 128 + k] : loW[(m - 128) * 128 + k];
            if (k == 0) g_bio[m] = (m < 128) ? lib[m] : lob[m - 128];
        }
    }
}

// ---------------- generic tiled GEMM: C op= act(A[aidx[M],K] @ Bw[N,K]^T + bias) ----------------
__global__ void __launch_bounds__(256) k_gemm(const float* __restrict__ A,
                                              const float* __restrict__ Bw,
                                              const float* __restrict__ bias,
                                              float* __restrict__ C,
                                              int M, int N, int K, int relu,
                                              const int* __restrict__ aidx, int accum) {
    __shared__ float As[64][33];
    __shared__ float Bs[64][33];
    int m0 = blockIdx.y * 64, n0 = blockIdx.x * 64;
    int tid = threadIdx.x;
    int tx = tid & 15, ty = tid >> 4;
    float acc[4][4] = {};
    for (int k0 = 0; k0 < K; k0 += 32) {
        #pragma unroll
        for (int i = 0; i < 2; i++) {
            int f = tid + 256 * i;
            int m = f >> 3, k4 = f & 7;
            int gm = m0 + m;
            float4 v = make_float4(0.f, 0.f, 0.f, 0.f);
            if (gm < M) {
                int am = aidx ? aidx[gm] : gm;
                v = *(const float4*)&A[am * K + k0 + k4 * 4];
            }
            As[m][k4 * 4 + 0] = v.x; As[m][k4 * 4 + 1] = v.y;
            As[m][k4 * 4 + 2] = v.z; As[m][k4 * 4 + 3] = v.w;
        }
        #pragma unroll
        for (int i = 0; i < 2; i++) {
            int f = tid + 256 * i;
            int n = f >> 3, k4 = f & 7;
            int gn = n0 + n;
            float4 v = make_float4(0.f, 0.f, 0.f, 0.f);
            if (gn < N) v = *(const float4*)&Bw[gn * K + k0 + k4 * 4];
            Bs[n][k4 * 4 + 0] = v.x; Bs[n][k4 * 4 + 1] = v.y;
            Bs[n][k4 * 4 + 2] = v.z; Bs[n][k4 * 4 + 3] = v.w;
        }
        __syncthreads();
        #pragma unroll
        for (int k = 0; k < 32; k++) {
            float a[4], b[4];
            #pragma unroll
            for (int r = 0; r < 4; r++) a[r] = As[ty * 4 + r][k];
            #pragma unroll
            for (int c = 0; c < 4; c++) b[c] = Bs[tx * 4 + c][k];
            #pragma unroll
            for (int r = 0; r < 4; r++)
                #pragma unroll
                for (int c = 0; c < 4; c++)
                    acc[r][c] += a[r] * b[c];
        }
        __syncthreads();
    }
    #pragma unroll
    for (int r = 0; r < 4; r++) {
        int gm = m0 + ty * 4 + r;
        if (gm < M) {
            #pragma unroll
            for (int c = 0; c < 4; c++) {
                int gn = n0 + tx * 4 + c;
                if (gn < N) {
                    float v = acc[r][c] + (bias ? bias[gn] : 0.f);
                    if (relu) v = fmaxf(v, 0.f);
                    if (accum) C[gm * N + gn] += v;
                    else       C[gm * N + gn] = v;
                }
            }
        }
    }
}

// ---------------- final add: out += uc ----------------
__global__ void k_add(float* __restrict__ out) {
    int i = blockIdx.x * blockDim.x + threadIdx.x;
    if (i < B * NC) out[i] += g_uc[i];
}

// ---------------- inp = adj @ ao, + h0 gather, into g_cat ----------------
#define PROP_SMEM ((L * L + L * 256) * 4)
__global__ void k_prop(const float* __restrict__ adj, const int* __restrict__ items,
                       const float* __restrict__ emb) {
    extern __shared__ float psm[];
    float* sA  = psm;
    float* sin = psm + L * L;
    int b = blockIdx.x, t = threadIdx.x;   // 256 threads
    for (int i = t; i < L * L; i += 256) sA[i] = adj[b * L * L + i];
    for (int k = 0; k < L; k++) sin[k * 256 + t] = g_ao[(b * L + k) * 256 + t];
    __syncthreads();
    for (int l = 0; l < L; l++) {
        float acc = 0.f;
        #pragma unroll 10
        for (int k = 0; k < L; k++)
            acc += sA[l * L + k] * sin[k * 256 + t];
        g_cat[(b * L + l) * 384 + t] = acc;
    }
    for (int i = t; i < L * H; i += 256) {
        int l = i >> 7, tt = i & 127;
        g_cat[(b * L + l) * 384 + 256 + tt] = emb[items[b * L + l] * H + tt];
    }
}

// ---------------- GRU elementwise + relu(sg) + pos emb + final + last + fp16 split ----------------
__global__ void k_gru_elem(const int* __restrict__ items, const int* __restrict__ lens,
                           const float* __restrict__ pos_emb) {
    int i = blockIdx.x * blockDim.x + threadIdx.x;
    int bl = i >> 7, t = i & 127;
    int b = bl / L, l = bl % L;
    const float* g = g_gates + bl * 512;
    float r = 1.f / (1.f + expf(-g[t]));
    float z = 1.f / (1.f + expf(-g[128 + t]));
    float n = tanhf(g[256 + t] + r * g[384 + t]);
    float h0 = g_cat[bl * 384 + 256 + t];
    float hn = n + z * (h0 - n);
    int item = items[bl];
    int len  = lens[b];
    int rev  = (item == 0) ? 0 : (len - 1 - l);
    float fin = fmaxf(g_sg[i], 0.f) + hn + pos_emb[rev * H + t];
    g_final[i] = fin;
    __half fh = __float2half(fin);
    g_fh[(b * LP + l) * H + t] = fh;
    g_fl[(b * LP + l) * H + t] = __float2half(fin - __half2float(fh));
    if (l == len - 1) g_last[b * H + t] = fin;
}

// ---------------- candidate fp16 convert ----------------
__global__ void k_cvt_cand() {
    int i = blockIdx.x * blockDim.x + threadIdx.x;   // NCP*H
    int n = i >> 7;
    float vT = 0.f, vA = 0.f;
    if (n < NC) { vT = g_cT[i]; vA = g_cA[i]; }
    g_cTh[i] = __float2half(vT);
    g_cAh[i] = __float2half(vA);
}

// ---------------- attention readout -> g_u ----------------
#define ATTN_SMEM ((L * 2 * H + H + 8 * 64 + 3 * H) * 4 + 64 * 4)
__global__ void k_attn(const int* __restrict__ items,
                       const float* __restrict__ ipw, const float* __restrict__ ipb,
                       const float* __restrict__ opw, const float* __restrict__ opb,
                       const float* __restrict__ w3) {
    extern __shared__ float sm[];
    float* kvs = sm;
    float* qs  = kvs + L * 2 * H;
    float* att = qs + H;
    float* ctx = att + 8 * 64;
    float* sg  = ctx + H;
    float* ls  = sg + H;
    int*   its = (int*)(ls + H);

    int b = blockIdx.x, t = threadIdx.x;
    for (int i = t; i < L * 2 * H; i += 256) kvs[i] = g_kv[b * L * 2 * H + i];
    if (t < H) ls[t] = g_last[b * H + t];
    if (t < L) its[t] = items[b * L + t];
    __syncthreads();

    if (t < H) {
        float a = ipb[t];
        const float* w = ipw + t * H;
        #pragma unroll 8
        for (int k = 0; k < H; k++) a += ls[k] * w[k];
        qs[t] = a;
    }
    __syncthreads();
    for (int i = t; i < 8 * L; i += 256) {
        int hd = i / L, l = i % L;
        float a = 0.f;
        #pragma unroll
        for (int d = 0; d < 16; d++) a += qs[hd * 16 + d] * kvs[l * 2 * H + hd * 16 + d];
        att[hd * 64 + l] = (its[l] == 0) ? -INFINITY : a * 0.25f;
    }
    __syncthreads();
    if (t < 8) {
        float m = -INFINITY;
        for (int l = 0; l < L; l++) m = fmaxf(m, att[t * 64 + l]);
        float s = 0.f;
        for (int l = 0; l < L; l++) {
            float e = expf(att[t * 64 + l] - m);
            att[t * 64 + l] = e;
            s += e;
        }
        float inv = 1.f / s;
        for (int l = 0; l < L; l++) att[t * 64 + l] *= inv;
    }
    __syncthreads();
    if (t < H) {
        int hd = t / 16;
        float c = 0.f;
        for (int l = 0; l < L; l++) c += att[hd * 64 + l] * kvs[l * 2 * H + H + t];
        ctx[t] = c;
    }
    __syncthreads();
    if (t < H) {
        float a = opb[t];
        const float* w = opw + t * H;
        #pragma unroll 8
        for (int k = 0; k < H; k++) a += ctx[k] * w[k];
        sg[t] = a;
    }
    __syncthreads();
    if (t < H) {
        float u = 0.f;
        const float* w1 = w3 + t * 3 * H + H;
        const float* w2 = w3 + t * 3 * H + 2 * H;
        #pragma unroll 8
        for (int k = 0; k < H; k++) u += ls[k] * w1[k] + sg[k] * w2[k];
        g_u[b * H + t] = u;
    }
}

// ---------------- tensor-core tail (transposed: M=candidates, N=l) ----------------
// smem: cT[128x128 fp16]=32K | cA=32K | F=[fh|fl][64x256 fp16]=32K | its
#define T_CT  0
#define T_CA  32768
#define T_F   65536
#define T_ITS 98304
#define TAIL_SMEM (T_ITS + 256)

__device__ __forceinline__ void ldsm_x4(uint32_t addr, uint32_t& r0, uint32_t& r1,
                                        uint32_t& r2, uint32_t& r3) {
    asm volatile("ldmatrix.sync.aligned.m8n8.x4.shared.b16 {%0,%1,%2,%3}, [%4];"
                 : "=r"(r0), "=r"(r1), "=r"(r2), "=r"(r3) : "r"(addr));
}
__device__ __forceinline__ void mma_fp16(float* d, uint32_t a0, uint32_t a1,
                                         uint32_t a2, uint32_t a3,
                                         uint32_t b0, uint32_t b1) {
    asm volatile(
        "mma.sync.aligned.m16n8k16.row.col.f32.f16.f16.f32 "
        "{%0,%1,%2,%3}, {%4,%5,%6,%7}, {%8,%9}, {%0,%1,%2,%3};"
        : "+f"(d[0]), "+f"(d[1]), "+f"(d[2]), "+f"(d[3])
        : "r"(a0), "r"(a1), "r"(a2), "r"(a3), "r"(b0), "r"(b1));
}
__device__ __forceinline__ uint32_t swz(uint32_t base, int row, int ch, int rs_ch) {
    return base + (uint32_t)(row * rs_ch * 16 + (((ch) ^ (row & 7)) << 4));
}

__global__ void __launch_bounds__(256, 2) k_tail(const int* __restrict__ items,
                                                 float* __restrict__ out) {
    extern __shared__ char smc[];
    uint32_t sb = (uint32_t)__cvta_generic_to_shared(smc);
    int*   its = (int*)(smc + T_ITS);

    int n0 = blockIdx.x * 128;
    int bg = blockIdx.y * 8;
    int t  = threadIdx.x;
    int w  = t >> 5, lane = t & 31;
    int mat = lane >> 3, rin = lane & 7;
    int g = lane >> 2, tg = lane & 3;
    int Rm = 16 * w;                          // warp's candidate-tile base row

    // ---- load candidate operands once (fp16, swizzled, 16-chunk rows) ----
    #pragma unroll
    for (int it = 0; it < 8; it++) {
        int idx = t + 256 * it;
        int r = idx >> 4, c = idx & 15;
        uint4 v = *(const uint4*)&g_cTh[(n0 + r) * H + c * 8];
        *(uint4*)(smc + T_CT + r * 256 + ((c ^ (r & 7)) << 4)) = v;
    }
    #pragma unroll
    for (int it = 0; it < 8; it++) {
        int idx = t + 256 * it;
        int r = idx >> 4, c = idx & 15;
        uint4 v = *(const uint4*)&g_cAh[(n0 + r) * H + c * 8];
        *(uint4*)(smc + T_CA + r * 256 + ((c ^ (r & 7)) << 4)) = v;
    }

    for (int bi = 0; bi < 8; bi++) {
        int b = bg + bi;
        // ---- load F = [fh|fl] for this batch (32-chunk rows) ----
        #pragma unroll
        for (int it = 0; it < 8; it++) {
            int idx = t + 256 * it;
            int r = idx >> 5, c = idx & 31;
            const __half* src = (c < 16) ? &g_fh[(b * LP + r) * H + c * 8]
                                         : &g_fl[(b * LP + r) * H + (c - 16) * 8];
            uint4 v = *(const uint4*)src;
            *(uint4*)(smc + T_F + r * 512 + ((c ^ (r & 7)) << 4)) = v;
        }
        if (t < 64) its[t] = (t < L) ? items[b * L + t] : 0;
        __syncthreads();

        // ---- MMA mainloop: Sacc[j] / Gacc[j] over 8 l-tiles ----
        // fh half: S and G; fl half: G only (S fl-correction dropped; softmax
        //   exponent perturbation ~2e-4 absolute, harmless at 1e-3 threshold)
        float Sacc[8][4] = {}, Gacc[8][4] = {};
        for (int kc = 0; kc < 8; kc++) {
            uint32_t aT[4], aA[4];
            int row_a = Rm + rin + ((mat & 1) << 3);
            int ch_a  = 2 * kc + (mat >> 1);
            ldsm_x4(swz(sb + T_CT, row_a, ch_a, 16), aT[0], aT[1], aT[2], aT[3]);
            ldsm_x4(swz(sb + T_CA, row_a, ch_a, 16), aA[0], aA[1], aA[2], aA[3]);
            int row_b = rin + ((mat >> 1) << 3);
            uint32_t bf[4][4];
            // fh half
            #pragma unroll
            for (int nh = 0; nh < 4; nh++)
                ldsm_x4(swz(sb + T_F, 16 * nh + row_b, 2 * kc + (mat & 1), 32),
                        bf[nh][0], bf[nh][1], bf[nh][2], bf[nh][3]);
            #pragma unroll
            for (int j = 0; j < 8; j++) {
                uint32_t b0 = bf[j >> 1][2 * (j & 1)], b1 = bf[j >> 1][2 * (j & 1) + 1];
                mma_fp16(Sacc[j], aT[0], aT[1], aT[2], aT[3], b0, b1);
                mma_fp16(Gacc[j], aA[0], aA[1], aA[2], aA[3], b0, b1);
            }
            // fl half (G only)
            #pragma unroll
            for (int nh = 0; nh < 4; nh++)
                ldsm_x4(swz(sb + T_F, 16 * nh + row_b, 16 + 2 * kc + (mat & 1), 32),
                        bf[nh][0], bf[nh][1], bf[nh][2], bf[nh][3]);
            #pragma unroll
            for (int j = 0; j < 8; j++) {
                uint32_t b0 = bf[j >> 1][2 * (j & 1)], b1 = bf[j >> 1][2 * (j & 1) + 1];
                mma_fp16(Gacc[j], aA[0], aA[1], aA[2], aA[3], b0, b1);
            }
        }

        // ---- in-register masked softmax over l + weighted G sum ----
        // thread holds rows {g, g+8} x l-cols {8j+2tg, 8j+2tg+1}
        unsigned mk0 = 0, mk1 = 0;
        #pragma unroll
        for (int j = 0; j < 8; j++) {
            if (its[8 * j + 2 * tg] != 0)     mk0 |= (1u << j);
            if (its[8 * j + 2 * tg + 1] != 0) mk1 |= (1u << j);
        }
        #pragma unroll
        for (int h = 0; h < 2; h++) {
            float m = -INFINITY;
            #pragma unroll
            for (int j = 0; j < 8; j++) {
                if (mk0 & (1u << j)) m = fmaxf(m, Sacc[j][2 * h]);
                if (mk1 & (1u << j)) m = fmaxf(m, Sacc[j][2 * h + 1]);
            }
            m = fmaxf(m, __shfl_xor_sync(0xFFFFFFFF, m, 1));
            m = fmaxf(m, __shfl_xor_sync(0xFFFFFFFF, m, 2));
            float s = 0.f, acc = 0.f;
            #pragma unroll
            for (int j = 0; j < 8; j++) {
                if (mk0 & (1u << j)) {
                    float e = __expf(Sacc[j][2 * h] - m);
                    s += e; acc += e * Gacc[j][2 * h];
                }
                if (mk1 & (1u << j)) {
                    float e = __expf(Sacc[j][2 * h + 1] - m);
                    s += e; acc += e * Gacc[j][2 * h + 1];
                }
            }
            s   += __shfl_xor_sync(0xFFFFFFFF, s, 1);
            s   += __shfl_xor_sync(0xFFFFFFFF, s, 2);
            acc += __shfl_xor_sync(0xFFFFFFFF, acc, 1);
            acc += __shfl_xor_sync(0xFFFFFFFF, acc, 2);
            if (tg == 0) {
                int gn = n0 + Rm + g + 8 * h;
                if (gn < NC) out[b * NC + gn] = acc / s;
            }
        }
        __syncthreads();   // protect sF/its before next batch overwrites
    }
}

// ---------------- host launcher ----------------
extern "C" void kernel_launch(void* const* d_in, const int* in_sizes, int n_in,
                              void* d_out, int out_size) {
    const int*   items = (const int*)d_in[0];
    const int*   lens  = (const int*)d_in[1];
    const float* adj   = (const float*)d_in[2];
    const int*   erow  = (const int*)d_in[3];
    const int*   ecol  = (const int*)d_in[4];
    const float* ew    = (const float*)d_in[5];
    const float* emb   = (const float*)d_in[6];
    const float* pos   = (const float*)d_in[7];
    const float* gW    = (const float*)d_in[8];
    const float* gb    = (const float*)d_in[9];
    const float* liW   = (const float*)d_in[10];
    const float* lib   = (const float*)d_in[11];
    const float* loW   = (const float*)d_in[12];
    const float* lob   = (const float*)d_in[13];
    const float* w_ih  = (const float*)d_in[14];
    const float* w_hh  = (const float*)d_in[15];
    const float* b_ih  = (const float*)d_in[16];
    const float* b_hh  = (const float*)d_in[17];
    const float* ipw   = (const float*)d_in[18];
    const float* ipb   = (const float*)d_in[19];
    const float* opw   = (const float*)d_in[20];
    const float* opb   = (const float*)d_in[21];
    const float* wt    = (const float*)d_in[22];
    const float* w3    = (const float*)d_in[23];
    float* out = (float*)d_out;

    // one-time resource creation (NOT during graph capture; first call only)
    static bool s_init = false;
    static cudaStream_t s1, s2, s3;
    static cudaEvent_t evRoot, evCand, evGru, evGE, evUC;
    if (!s_init) {
        cudaStreamCreateWithFlags(&s1, cudaStreamNonBlocking);
        cudaStreamCreateWithFlags(&s2, cudaStreamNonBlocking);
        cudaStreamCreateWithFlags(&s3, cudaStreamNonBlocking);
        cudaEventCreateWithFlags(&evRoot, cudaEventDisableTiming);
        cudaEventCreateWithFlags(&evCand, cudaEventDisableTiming);
        cudaEventCreateWithFlags(&evGru,  cudaEventDisableTiming);
        cudaEventCreateWithFlags(&evGE,   cudaEventDisableTiming);
        cudaEventCreateWithFlags(&evUC,   cudaEventDisableTiming);
        cudaFuncSetAttribute(k_attn, cudaFuncAttributeMaxDynamicSharedMemorySize, ATTN_SMEM);
        cudaFuncSetAttribute(k_tail, cudaFuncAttributeMaxDynamicSharedMemorySize, TAIL_SMEM);
        cudaFuncSetAttribute(k_prop, cudaFuncAttributeMaxDynamicSharedMemorySize, PROP_SMEM);
        s_init = true;
    }

    float* p_agg;   cudaGetSymbolAddress((void**)&p_agg,   g_agg);
    int*   p_mark;  cudaGetSymbolAddress((void**)&p_mark,  g_mark);
    float* p_sg;    cudaGetSymbolAddress((void**)&p_sg,    g_sg);
    float* p_ao;    cudaGetSymbolAddress((void**)&p_ao,    g_ao);
    float* p_cat;   cudaGetSymbolAddress((void**)&p_cat,   g_cat);
    float* p_gates; cudaGetSymbolAddress((void**)&p_gates, g_gates);
    float* p_final; cudaGetSymbolAddress((void**)&p_final, g_final);
    float* p_kv;    cudaGetSymbolAddress((void**)&p_kv,    g_kv);
    float* p_u;     cudaGetSymbolAddress((void**)&p_u,     g_u);
    float* p_uc;    cudaGetSymbolAddress((void**)&p_uc,    g_uc);
    float* p_cT;    cudaGetSymbolAddress((void**)&p_cT,    g_cT);
    float* p_cA;    cudaGetSymbolAddress((void**)&p_cA,    g_cA);
    float* p_w3a;   cudaGetSymbolAddress((void**)&p_w3a,   g_w3a);
    float* p_Wc;    cudaGetSymbolAddress((void**)&p_Wc,    g_Wc);
    float* p_bc;    cudaGetSymbolAddress((void**)&p_bc,    g_bc);
    float* p_Wio;   cudaGetSymbolAddress((void**)&p_Wio,   g_Wio);
    float* p_bio;   cudaGetSymbolAddress((void**)&p_bio,   g_bio);
    void*  p_fh;    cudaGetSymbolAddress(&p_fh,  g_fh);
    void*  p_fl;    cudaGetSymbolAddress(&p_fl,  g_fl);

    const int M = B * L;   // 3200

    cudaEventRecord(evRoot, 0);
    cudaStreamWaitEvent(s1, evRoot, 0);
    cudaStreamWaitEvent(s2, evRoot, 0);

    // ---- s1: candidate chain ----
    k_w3t<<<H, H, 0, s1>>>(w3);
    {
        dim3 gC(2, (NC + 63) / 64);
        k_gemm<<<gC, 256, 0, s1>>>(emb + H, wt,    (const float*)nullptr, p_cT, NC, H, H, 0, nullptr, 0);
        k_gemm<<<gC, 256, 0, s1>>>(emb + H, p_w3a, (const float*)nullptr, p_cA, NC, H, H, 0, nullptr, 0);
    }
    k_cvt_cand<<<(NCP * H) / 256, 256, 0, s1>>>();
    cudaEventRecord(evCand, s1);

    // ---- s2: GRU chain (independent of edge scatter) ----
    k_prep<<<768, 384, 0, s2>>>(liW, lib, loW, lob, w_ih, w_hh, b_ih, b_hh);
    {
        dim3 gA(4, (M + 63) / 64);    // N=256: [ain|aout] = emb[items] @ Wio^T
        k_gemm<<<gA, 256, 0, s2>>>(emb, p_Wio, p_bio, p_ao, M, 256, H, 0, items, 0);
    }
    k_prop<<<B, 256, PROP_SMEM, s2>>>(adj, items, emb);
    {
        dim3 gG(8, (M + 63) / 64);    // N=512: gates = cat @ Wc^T
        k_gemm<<<gG, 256, 0, s2>>>(p_cat, p_Wc, p_bc, p_gates, M, 512, 384, 0, nullptr, 0);
    }
    cudaEventRecord(evGru, s2);

    // ---- s0: edge scatter + sg ----
    cudaMemsetAsync(p_agg, 0, NI * H * sizeof(float));
    cudaMemsetAsync(p_mark, 0, NI * sizeof(int));
    cudaMemsetAsync(p_fh, 0, B * LP * H * sizeof(__half));
    cudaMemsetAsync(p_fl, 0, B * LP * H * sizeof(__half));
    k_mark<<<(B * L + 255) / 256, 256>>>(items);
    k_edge<<<(E * 32 + 255) / 256, 256>>>(erow, ecol, ew, emb);
    {
        dim3 gS(2, (M + 63) / 64);    // sg_pre = agg[items] @ gW^T + gb (relu deferred)
        k_gemm<<<gS, 256>>>(p_agg, gW, gb, p_sg, M, H, H, 0, items, 0);
    }

    // join gru chain -> elementwise
    cudaStreamWaitEvent(0, evGru, 0);
    k_gru_elem<<<(M * H) / 256, 256>>>(items, lens, pos);
    cudaEventRecord(evGE, 0);

    // ---- s3: attention branch + uc GEMM (runs concurrently with tail) ----
    cudaStreamWaitEvent(s3, evGE, 0);
    {
        dim3 gKV(4, (M + 63) / 64);
        k_gemm<<<gKV, 256, 0, s3>>>(p_final, ipw + H * H, ipb + H, p_kv, M, 2 * H, H, 0, nullptr, 0);
    }
    k_attn<<<B, 256, ATTN_SMEM, s3>>>(items, ipw, ipb, opw, opb, w3);
    {
        dim3 gU((NC + 63) / 64, 1);   // uc = u @ cand^T -> g_uc (separate buffer)
        k_gemm<<<gU, 256, 0, s3>>>(p_u, emb + H, (const float*)nullptr, p_uc, B, NC, H, 0, nullptr, 0);
    }
    cudaEventRecord(evUC, s3);

    // ---- s0: fp16 mma tail (writes scores), then cheap elementwise add ----
    cudaStreamWaitEvent(0, evCand, 0);
    k_tail<<<dim3(NCP / 128, B / 8), 256, TAIL_SMEM>>>(items, out);

    cudaStreamWaitEvent(0, evUC, 0);
    k_add<<<(B * NC + 255) / 256, 256>>>(out);
}